// round 13
// baseline (speedup 1.0000x reference)
#include <cuda_runtime.h>
#include <cuda_fp16.h>
#include <math.h>
#include <stdint.h>

#define BATCH 16
#define HDIM 128
#define WDIM 128
#define HID 64

typedef uint32_t u32;
typedef uint16_t u16;

// h1 buffer (NHWC fp32): layer1 writes, attention pass 1 reads
__device__ __align__(16) float g_buf0[BATCH * HDIM * WDIM * HID];
// padded f16 activations for layer-1 conv: [16][130][130][64]
__device__ __align__(16) __half g_h16[BATCH * 130 * 130 * HID];
// f16 layer-1 weights: [tap 9][gate*64+oc 320][cin 64]
__device__ __align__(16) __half g_w1h[9 * 320 * 64];
// f16 attention weights hi/lo (Markidis split): per layer qkv [192][64], proj [64][64]
__device__ __align__(16) __half g_wqh[2][192 * 64];
__device__ __align__(16) __half g_wql[2][192 * 64];
__device__ __align__(16) __half g_wph[2][64 * 64];
__device__ __align__(16) __half g_wpl[2][64 * 64];

__device__ __forceinline__ float sigm(float v) {
    return __fdividef(1.0f, 1.0f + __expf(-v));
}
__device__ __forceinline__ float ftanh(float v) {
    return 1.0f - __fdividef(2.0f, __expf(2.0f * v) + 1.0f);
}

// ===================== sm_80+ tensor helpers (no 'a' target) ================
__device__ __forceinline__ u32 smem_u32(const void* p) {
    u32 a;
    asm("{ .reg .u64 t; cvta.to.shared.u64 t, %1; cvt.u32.u64 %0, t; }"
        : "=r"(a) : "l"(p));
    return a;
}
__device__ __forceinline__ void cp16(u32 dst, const void* src) {
    asm volatile("cp.async.cg.shared.global [%0], [%1], 16;" :: "r"(dst), "l"(src));
}
#define CPASYNC_COMMIT() asm volatile("cp.async.commit_group;" ::: "memory")
#define CPASYNC_WAIT0()  asm volatile("cp.async.wait_group 0;" ::: "memory")

__device__ __forceinline__ void ldsm4(u32* r, u32 a) {
    asm volatile("ldmatrix.sync.aligned.m8n8.x4.shared.b16 {%0,%1,%2,%3}, [%4];"
                 : "=r"(r[0]), "=r"(r[1]), "=r"(r[2]), "=r"(r[3]) : "r"(a));
}
__device__ __forceinline__ void mma16816(float* c, const u32* a, u32 b0, u32 b1) {
    asm volatile(
        "mma.sync.aligned.m16n8k16.row.col.f32.f16.f16.f32 "
        "{%0,%1,%2,%3}, {%4,%5,%6,%7}, {%8,%9}, {%0,%1,%2,%3};"
        : "+f"(c[0]), "+f"(c[1]), "+f"(c[2]), "+f"(c[3])
        : "r"(a[0]), "r"(a[1]), "r"(a[2]), "r"(a[3]), "r"(b0), "r"(b1));
}
__device__ __forceinline__ u32 pk2(float lo, float hi) {   // {lo | hi<<16}
    u32 r;
    asm("cvt.rn.f16x2.f32 %0, %1, %2;" : "=r"(r) : "f"(hi), "f"(lo));
    return r;
}
// f16 hi/lo split of a float pair
__device__ __forceinline__ void split2(float a, float b, u32& hi, u32& lo) {
    __half ha = __float2half_rn(a), hb = __float2half_rn(b);
    hi = ((u32)__half_as_ushort(hb) << 16) | (u32)__half_as_ushort(ha);
    lo = pk2(a - __half2float(ha), b - __half2float(hb));
}
__device__ __forceinline__ void sts32(u32 addr, u32 v) {
    asm volatile("st.shared.b32 [%0], %1;" :: "r"(addr), "r"(v));
}
__device__ __forceinline__ void sts16(u32 addr, float v) {
    u16 b = __half_as_ushort(__float2half_rn(v));
    asm volatile("st.shared.b16 [%0], %1;" :: "r"(addr), "h"(b) : "memory");
}

// ---------------------------------------------------------------------------
// Merged prep: layer-1 weight repack + border zero + attention weight repack
// ---------------------------------------------------------------------------
#define PREP_A (9 * 320 * 64)          // 184320
#define PREP_B (BATCH * 130 * 130)     // 270400
#define PREP_C (192 * 64)              // 12288
#define PREP_D (64 * 64)               // 4096
#define PREP_TOTAL (PREP_A + PREP_B + PREP_C + PREP_D)

__global__ void prep_all(const float* __restrict__ cw,
                         const float* __restrict__ pxw,
                         const float* __restrict__ pyw,
                         const float* __restrict__ q0, const float* __restrict__ p0,
                         const float* __restrict__ q1, const float* __restrict__ p1) {
    int idx = blockIdx.x * 256 + threadIdx.x;
    if (idx < PREP_A) {
        int tap = idx / (320 * 64);
        int rem = idx % (320 * 64);
        int r = rem / 64, cin = rem % 64;
        int g = r >> 6, n = r & 63;
        float v;
        if (g == 0)      v = cw[(n * 128 + cin) * 9 + tap];
        else if (g == 1) v = cw[((128 + n) * 128 + cin) * 9 + tap];
        else if (g == 2) v = cw[((192 + n) * 128 + cin) * 9 + tap];
        else if (g == 3) v = pxw[(n * 64 + cin) * 9 + tap];
        else             v = pyw[(n * 64 + cin) * 9 + tap];
        g_w1h[idx] = __float2half_rn(v);
        return;
    }
    idx -= PREP_A;
    if (idx < PREP_B) {
        int bp = idx % (130 * 130);
        int yy = bp / 130, xx = bp % 130;
        if (yy == 0 || yy == 129 || xx == 0 || xx == 129) {
            uint4* d = (uint4*)(g_h16 + (size_t)idx * 64);
            uint4 z = {0, 0, 0, 0};
#pragma unroll
            for (int i = 0; i < 8; i++) d[i] = z;
        }
        return;
    }
    idx -= PREP_B;
    if (idx < PREP_C) {
        float v0 = q0[idx], v1 = q1[idx];
        __half h0 = __float2half_rn(v0), h1 = __float2half_rn(v1);
        g_wqh[0][idx] = h0; g_wql[0][idx] = __float2half_rn(v0 - __half2float(h0));
        g_wqh[1][idx] = h1; g_wql[1][idx] = __float2half_rn(v1 - __half2float(h1));
        return;
    }
    idx -= PREP_C;
    if (idx < PREP_D) {
        float v0 = p0[idx], v1 = p1[idx];
        __half h0 = __float2half_rn(v0), h1 = __float2half_rn(v1);
        g_wph[0][idx] = h0; g_wpl[0][idx] = __float2half_rn(v0 - __half2float(h0));
        g_wph[1][idx] = h1; g_wpl[1][idx] = __float2half_rn(v1 - __half2float(h1));
    }
}

// ---------------------------------------------------------------------------
// Window attention on mma.sync with f16 hi/lo compensation, 8 warps/window.
// from_x=1: compute layer-0 gates in-kernel from the raw input patch (fused
// layer0), write h0 hi/lo into the X planes. from_x=0: load h1 from g_buf0.
// to_h16=1: epilogue writes padded f16 g_h16; to_h16=0: fused 1x1 conv -> out.
// ---------------------------------------------------------------------------
#define AT_XH 0
#define AT_XL 8192
#define AT_QH 16384
#define AT_QL 24576
#define AT_KH 32768
#define AT_KL 40960
#define AT_VTH 49152
#define AT_VTL 57344
#define AT_WQH 65536
#define AT_WQL 90112
#define AT_RED 114688
#define AT_SMEM 115200

__global__ __launch_bounds__(256, 2) void win_attn_tc(
    int layer, const float* __restrict__ projb,
    const float* __restrict__ outw, const float* __restrict__ outb,
    float* __restrict__ out, int to_h16,
    const float* __restrict__ x0, const float* __restrict__ cw0,
    const float* __restrict__ cb0, const float* __restrict__ pxw0,
    const float* __restrict__ pyw0, int from_x) {
    extern __shared__ char smem[];
    u32 sb = smem_u32(smem);
    int tid = threadIdx.x, lane = tid & 31, w = tid >> 5;
    int wid = blockIdx.x;
    int b = wid >> 8, wy = (wid >> 4) & 15, wx = wid & 15;
    int base = ((b * 128 + wy * 8) * 128 + wx * 8) * 64;

    // ---- stage qkv weights hi/lo ----
    if (tid < 192) {
        int r = tid;
        const __half* sh = g_wqh[layer] + r * 64;
        const __half* sl = g_wql[layer] + r * 64;
        u32 row = (u32)r * 128, sw = (u32)((r & 7) << 4);
#pragma unroll
        for (int i = 0; i < 8; i++) {
            cp16(sb + AT_WQH + ((row + i * 16) ^ sw), (const char*)sh + i * 16);
            cp16(sb + AT_WQL + ((row + i * 16) ^ sw), (const char*)sl + i * 16);
        }
    }
    CPASYNC_COMMIT();

    if (from_x) {
        // ---- fused layer-0: stage weights (into K region) + patch (VT) ----
        float* s_w = (float*)(smem + AT_KH);        // [64][48]
        float* s_b = s_w + 64 * 48;                 // [192]
        float* s_patch = (float*)(smem + AT_VTH);   // [10][10]
        for (int i = tid; i < 64 * 45; i += 256) {
            int c = i / 45, j = i % 45;
            int g2 = j / 9, tap = j % 9;
            float v;
            if (g2 == 0)      v = cw0[c * 585 + tap];
            else if (g2 == 1) v = cw0[(128 + c) * 585 + tap];
            else if (g2 == 2) v = cw0[(192 + c) * 585 + tap];
            else if (g2 == 3) v = pxw0[c * 9 + tap];
            else              v = pyw0[c * 9 + tap];
            s_w[c * 48 + j] = v;
        }
        if (tid < 192) {
            int k = tid >> 6, c = tid & 63;
            int off = (k == 0) ? 0 : (k == 1 ? 128 : 192);
            s_b[tid] = cb0[off + c];
        }
        if (tid < 100) {
            int r10 = tid / 10, c10 = tid % 10;
            int gy = wy * 8 + r10 - 1, gx = wx * 8 + c10 - 1;
            float v = 0.0f;
            if (gy >= 0 && gy < 128 && gx >= 0 && gx < 128)
                v = x0[(b * 128 + gy) * 128 + gx];
            s_patch[tid] = v;
        }
        __syncthreads();

        // thread = (token group of 4, channel group of 4)
        int tg = tid >> 4, cg2 = tid & 15;
        int ty = tg >> 1, tx0 = (tg & 1) * 4;
        int c0 = cg2 * 4;
        float patch[3][6];
#pragma unroll
        for (int ky = 0; ky < 3; ky++)
#pragma unroll
            for (int kx = 0; kx < 6; kx++)
                patch[ky][kx] = s_patch[(ty + ky) * 10 + tx0 + kx];

#pragma unroll
        for (int ch = 0; ch < 4; ch++) {
            int c = c0 + ch;
            float wv[48];
            const float4* w4 = (const float4*)(s_w + c * 48);
#pragma unroll
            for (int q2 = 0; q2 < 12; q2++) {
                float4 t4 = w4[q2];
                wv[q2 * 4 + 0] = t4.x; wv[q2 * 4 + 1] = t4.y;
                wv[q2 * 4 + 2] = t4.z; wv[q2 * 4 + 3] = t4.w;
            }
            float b0 = s_b[c], b1 = s_b[64 + c], b2 = s_b[128 + c];
#pragma unroll
            for (int i = 0; i < 4; i++) {
                float aci = 0.f, aco = 0.f, acg = 0.f, apx = 0.f, apy = 0.f;
#pragma unroll
                for (int ky = 0; ky < 3; ky++)
#pragma unroll
                    for (int kx = 0; kx < 3; kx++) {
                        float a = patch[ky][i + kx];
                        int tap = ky * 3 + kx;
                        aci += a * wv[tap];
                        aco += a * wv[9 + tap];
                        acg += a * wv[18 + tap];
                        apx += a * wv[27 + tap];
                        apy += a * wv[36 + tap];
                    }
                float ig = sigm(aci + apx + b0);
                float og = sigm(aco + apy + b1);
                float gg = ftanh(acg + apy + b2);
                float h = og * ftanh(ig * gg);
                int r = ty * 8 + tx0 + i;
                u32 off = ((u32)(r * 128 + c * 2)) ^ ((u32)(r & 7) << 4);
                __half hh = __float2half_rn(h);
                sts16(sb + AT_XH + off, h);
                sts16(sb + AT_XL + off, h - __half2float(hh));
            }
        }
    } else {
        int row = tid >> 2, q = tid & 3;              // token row, 16-col quarter
        int ty = row >> 3, tx = row & 7;
        const float* src = g_buf0 + base + (ty * 128 + tx) * 64 + q * 16;
        u32 sw = (u32)((row & 7) << 4);
#pragma unroll
        for (int j = 0; j < 4; j++) {
            float4 a = *(const float4*)(src + j * 4);
            u32 byte0 = (u32)(row * 128 + q * 32 + j * 8);
            u32 h01, l01, h23, l23;
            split2(a.x, a.y, h01, l01);
            split2(a.z, a.w, h23, l23);
            sts32(sb + AT_XH + (byte0 ^ sw), h01);
            sts32(sb + AT_XL + (byte0 ^ sw), l01);
            sts32(sb + AT_XH + ((byte0 + 4) ^ sw), h23);
            sts32(sb + AT_XL + ((byte0 + 4) ^ sw), l23);
        }
    }
    CPASYNC_WAIT0();
    __syncthreads();

    // lane-invariant ldsm address pieces
    int aRow = (lane & 7) + 8 * ((lane >> 3) & 1);
    u32 aKl = (u32)(16 * (lane >> 4));
    int bRow = ((lane >> 4) & 1) * 8 + (lane & 7);
    u32 bKl = (u32)(((lane >> 3) & 1) * 16);
    int g = lane >> 2, t = lane & 3;

    // ---- phase 1: QKV GEMM (3-term). warp = (ocg, mh) ----
    {
        int ocg = w >> 1, mh = w & 1;
        float c[2][6][4];
#pragma unroll
        for (int mtl = 0; mtl < 2; mtl++)
#pragma unroll
            for (int nt = 0; nt < 6; nt++)
#pragma unroll
                for (int e = 0; e < 4; e++) c[mtl][nt][e] = 0.0f;

#pragma unroll
        for (int ks = 0; ks < 4; ks++) {
            u32 ah[2][4], al[2][4];
#pragma unroll
            for (int mtl = 0; mtl < 2; mtl++) {
                u32 ar = (u32)((mh * 2 + mtl) * 16 + aRow);
                u32 off = ar * 128 + (u32)(ks * 32) + aKl;
                u32 sw = ((ar & 7) << 4);
                ldsm4(ah[mtl], sb + AT_XH + (off ^ sw));
                ldsm4(al[mtl], sb + AT_XL + (off ^ sw));
            }
#pragma unroll
            for (int np = 0; np < 3; np++) {
                u32 bh[4], bl[4];
                u32 nr = (u32)(ocg * 48 + np * 16 + bRow);
                u32 off = nr * 128 + (u32)(ks * 32) + bKl;
                u32 sw = ((nr & 7) << 4);
                ldsm4(bh, sb + AT_WQH + (off ^ sw));
                ldsm4(bl, sb + AT_WQL + (off ^ sw));
#pragma unroll
                for (int mtl = 0; mtl < 2; mtl++) {
                    mma16816(c[mtl][np * 2], ah[mtl], bh[0], bh[1]);
                    mma16816(c[mtl][np * 2], al[mtl], bh[0], bh[1]);
                    mma16816(c[mtl][np * 2], ah[mtl], bl[0], bl[1]);
                    mma16816(c[mtl][np * 2 + 1], ah[mtl], bh[2], bh[3]);
                    mma16816(c[mtl][np * 2 + 1], al[mtl], bh[2], bh[3]);
                    mma16816(c[mtl][np * 2 + 1], ah[mtl], bl[2], bl[3]);
                }
            }
        }
        // store Q (x0.25), K, V^T as f16 hi/lo
#pragma unroll
        for (int mtl = 0; mtl < 2; mtl++) {
            int mt = (w & 1) * 2 + mtl;
#pragma unroll
            for (int nt = 0; nt < 6; nt++) {
                int nc = ocg * 48 + nt * 8 + t * 2;
                int r0 = mt * 16 + g, r1 = r0 + 8;
                float v0 = c[mtl][nt][0], v1 = c[mtl][nt][1];
                float v2 = c[mtl][nt][2], v3 = c[mtl][nt][3];
                u32 sw0 = ((u32)(r0 & 7) << 4), sw1 = ((u32)(r1 & 7) << 4);
                if (nc < 64) {
                    u32 h01, l01, h23, l23;
                    split2(v0 * 0.25f, v1 * 0.25f, h01, l01);
                    split2(v2 * 0.25f, v3 * 0.25f, h23, l23);
                    u32 o0 = ((u32)(r0 * 128 + nc * 2)) ^ sw0;
                    u32 o1 = ((u32)(r1 * 128 + nc * 2)) ^ sw1;
                    sts32(sb + AT_QH + o0, h01); sts32(sb + AT_QL + o0, l01);
                    sts32(sb + AT_QH + o1, h23); sts32(sb + AT_QL + o1, l23);
                } else if (nc < 128) {
                    int kc = nc - 64;
                    u32 h01, l01, h23, l23;
                    split2(v0, v1, h01, l01);
                    split2(v2, v3, h23, l23);
                    u32 o0 = ((u32)(r0 * 128 + kc * 2)) ^ sw0;
                    u32 o1 = ((u32)(r1 * 128 + kc * 2)) ^ sw1;
                    sts32(sb + AT_KH + o0, h01); sts32(sb + AT_KL + o0, l01);
                    sts32(sb + AT_KH + o1, h23); sts32(sb + AT_KL + o1, l23);
                } else {
                    int d0 = nc - 128, d1 = d0 + 1;
                    u32 s0 = (u32)((d0 & 7) << 4), s1 = (u32)((d1 & 7) << 4);
                    float vv[4] = {v0, v1, v2, v3};
                    int dd[4] = {d0, d1, d0, d1};
                    int rr[4] = {r0, r0, r1, r1};
                    u32 ss[4] = {s0, s1, s0, s1};
#pragma unroll
                    for (int e = 0; e < 4; e++) {
                        __half h = __float2half_rn(vv[e]);
                        float rl = vv[e] - __half2float(h);
                        u32 off = ((u32)(dd[e] * 128 + rr[e] * 2)) ^ ss[e];
                        sts16(sb + AT_VTH + off, vv[e]);
                        sts16(sb + AT_VTL + off, rl);
                    }
                }
            }
        }
    }
    __syncthreads();

    // ---- phase 2: attention, warp = (head, mt-half) ----
    {
        int h = w >> 1, mh = w & 1;
        u32 kbh[4][4], kbl[4][4], vbh[4][4], vbl[4][4];
#pragma unroll
        for (int np = 0; np < 4; np++) {
            u32 nr = (u32)(np * 16 + bRow);
            u32 off = nr * 128 + (u32)(h * 32) + bKl;
            u32 sw = ((nr & 7) << 4);
            ldsm4(kbh[np], sb + AT_KH + (off ^ sw));
            ldsm4(kbl[np], sb + AT_KL + (off ^ sw));
        }
#pragma unroll
        for (int ks = 0; ks < 4; ks++) {
            u32 nr = (u32)(h * 16 + bRow);
            u32 off = nr * 128 + (u32)(ks * 32) + bKl;
            u32 sw = ((nr & 7) << 4);
            ldsm4(vbh[ks], sb + AT_VTH + (off ^ sw));
            ldsm4(vbl[ks], sb + AT_VTL + (off ^ sw));
        }
        __syncthreads();   // all warps hold K/V fragments; vt planes now free
        // stage proj weights into the vt planes (overlap with compute)
        if (tid < 128) {
            int r = tid & 63;
            const __half* src = (tid < 64) ? (g_wph[layer] + r * 64)
                                           : (g_wpl[layer] + r * 64);
            u32 dstb = (tid < 64) ? (sb + AT_VTH) : (sb + AT_VTL);
            u32 row = (u32)r * 128, sw = (u32)((r & 7) << 4);
#pragma unroll
            for (int i = 0; i < 8; i++)
                cp16(dstb + ((row + i * 16) ^ sw), (const char*)src + i * 16);
        }
        CPASYNC_COMMIT();

#pragma unroll
        for (int mtl = 0; mtl < 2; mtl++) {
            int mt = mh * 2 + mtl;
            u32 aqh[4], aql[4];
            u32 ar = (u32)(mt * 16 + aRow);
            u32 off = ar * 128 + (u32)(h * 32) + aKl;
            u32 sw = ((ar & 7) << 4);
            ldsm4(aqh, sb + AT_QH + (off ^ sw));
            ldsm4(aql, sb + AT_QL + (off ^ sw));

            float s[8][4];
#pragma unroll
            for (int nt = 0; nt < 8; nt++)
#pragma unroll
                for (int e = 0; e < 4; e++) s[nt][e] = 0.0f;
#pragma unroll
            for (int np = 0; np < 4; np++) {
                mma16816(s[np * 2], aqh, kbh[np][0], kbh[np][1]);
                mma16816(s[np * 2], aql, kbh[np][0], kbh[np][1]);
                mma16816(s[np * 2], aqh, kbl[np][0], kbl[np][1]);
                mma16816(s[np * 2 + 1], aqh, kbh[np][2], kbh[np][3]);
                mma16816(s[np * 2 + 1], aql, kbh[np][2], kbh[np][3]);
                mma16816(s[np * 2 + 1], aqh, kbl[np][2], kbl[np][3]);
            }
            // softmax rows (mt*16+g) and (+8)
            float m0 = -1e30f, m1 = -1e30f;
#pragma unroll
            for (int nt = 0; nt < 8; nt++) {
                m0 = fmaxf(m0, fmaxf(s[nt][0], s[nt][1]));
                m1 = fmaxf(m1, fmaxf(s[nt][2], s[nt][3]));
            }
            m0 = fmaxf(m0, __shfl_xor_sync(0xffffffff, m0, 1));
            m0 = fmaxf(m0, __shfl_xor_sync(0xffffffff, m0, 2));
            m1 = fmaxf(m1, __shfl_xor_sync(0xffffffff, m1, 1));
            m1 = fmaxf(m1, __shfl_xor_sync(0xffffffff, m1, 2));
            float s0 = 0.f, s1 = 0.f;
#pragma unroll
            for (int nt = 0; nt < 8; nt++) {
                s[nt][0] = __expf(s[nt][0] - m0); s0 += s[nt][0];
                s[nt][1] = __expf(s[nt][1] - m0); s0 += s[nt][1];
                s[nt][2] = __expf(s[nt][2] - m1); s1 += s[nt][2];
                s[nt][3] = __expf(s[nt][3] - m1); s1 += s[nt][3];
            }
            s0 += __shfl_xor_sync(0xffffffff, s0, 1);
            s0 += __shfl_xor_sync(0xffffffff, s0, 2);
            s1 += __shfl_xor_sync(0xffffffff, s1, 1);
            s1 += __shfl_xor_sync(0xffffffff, s1, 2);
            float i0 = 1.0f / s0, i1 = 1.0f / s1;

            float o[2][4];
#pragma unroll
            for (int nt = 0; nt < 2; nt++)
#pragma unroll
                for (int e = 0; e < 4; e++) o[nt][e] = 0.0f;
#pragma unroll
            for (int ks = 0; ks < 4; ks++) {
                u32 ph[4], pl[4];
                split2(s[2 * ks][0], s[2 * ks][1], ph[0], pl[0]);
                split2(s[2 * ks][2], s[2 * ks][3], ph[1], pl[1]);
                split2(s[2 * ks + 1][0], s[2 * ks + 1][1], ph[2], pl[2]);
                split2(s[2 * ks + 1][2], s[2 * ks + 1][3], ph[3], pl[3]);
                mma16816(o[0], ph, vbh[ks][0], vbh[ks][1]);
                mma16816(o[0], pl, vbh[ks][0], vbh[ks][1]);
                mma16816(o[0], ph, vbl[ks][0], vbl[ks][1]);
                mma16816(o[1], ph, vbh[ks][2], vbh[ks][3]);
                mma16816(o[1], pl, vbh[ks][2], vbh[ks][3]);
                mma16816(o[1], ph, vbl[ks][2], vbl[ks][3]);
            }
            // scale + store O hi/lo to x planes
            int r0 = mt * 16 + g, r1 = r0 + 8;
            u32 sw0 = ((u32)(r0 & 7) << 4), sw1 = ((u32)(r1 & 7) << 4);
#pragma unroll
            for (int nt = 0; nt < 2; nt++) {
                int dc = h * 16 + nt * 8 + t * 2;
                u32 h01, l01, h23, l23;
                split2(o[nt][0] * i0, o[nt][1] * i0, h01, l01);
                split2(o[nt][2] * i1, o[nt][3] * i1, h23, l23);
                u32 o0 = ((u32)(r0 * 128 + dc * 2)) ^ sw0;
                u32 o1 = ((u32)(r1 * 128 + dc * 2)) ^ sw1;
                sts32(sb + AT_XH + o0, h01); sts32(sb + AT_XL + o0, l01);
                sts32(sb + AT_XH + o1, h23); sts32(sb + AT_XL + o1, l23);
            }
        }
    }
    CPASYNC_WAIT0();
    __syncthreads();

    // ---- phase 3: proj GEMM (3-term), warp = (m-tile, n-half) ----
    {
        int mtile = w >> 1, nh = w & 1;
        float c[4][4];
#pragma unroll
        for (int nt = 0; nt < 4; nt++)
#pragma unroll
            for (int e = 0; e < 4; e++) c[nt][e] = 0.0f;
#pragma unroll
        for (int ks = 0; ks < 4; ks++) {
            u32 ah[4], al[4];
            u32 ar = (u32)(mtile * 16 + aRow);
            u32 off = ar * 128 + (u32)(ks * 32) + aKl;
            u32 sw = ((ar & 7) << 4);
            ldsm4(ah, sb + AT_XH + (off ^ sw));
            ldsm4(al, sb + AT_XL + (off ^ sw));
#pragma unroll
            for (int npl = 0; npl < 2; npl++) {
                int np = nh * 2 + npl;
                u32 bh[4], bl[4];
                u32 nr = (u32)(np * 16 + bRow);
                u32 boff = nr * 128 + (u32)(ks * 32) + bKl;
                u32 bsw = ((nr & 7) << 4);
                ldsm4(bh, sb + AT_VTH + (boff ^ bsw));
                ldsm4(bl, sb + AT_VTL + (boff ^ bsw));
                mma16816(c[npl * 2], ah, bh[0], bh[1]);
                mma16816(c[npl * 2], al, bh[0], bh[1]);
                mma16816(c[npl * 2], ah, bl[0], bl[1]);
                mma16816(c[npl * 2 + 1], ah, bh[2], bh[3]);
                mma16816(c[npl * 2 + 1], al, bh[2], bh[3]);
                mma16816(c[npl * 2 + 1], ah, bl[2], bl[3]);
            }
        }
        if (to_h16) {
#pragma unroll
            for (int ntl = 0; ntl < 4; ntl++) {
                int nt = nh * 4 + ntl;
                int cc = nt * 8 + t * 2;
                float b0 = __ldg(projb + cc), b1 = __ldg(projb + cc + 1);
#pragma unroll
                for (int rh = 0; rh < 2; rh++) {
                    int tok = mtile * 16 + g + rh * 8;
                    int ty = tok >> 3, tx = tok & 7;
                    float v0 = c[ntl][rh * 2] + b0, v1 = c[ntl][rh * 2 + 1] + b1;
                    int gy = wy * 8 + ty, gx = wx * 8 + tx;
                    __half* dst = g_h16 +
                        ((size_t)((b * 130 + gy + 1) * 130 + gx + 1)) * 64 + cc;
                    *(__half2*)dst = __floats2half2_rn(v0, v1);
                }
            }
        } else {
            float* s_red = (float*)(smem + AT_RED);    // [4 mtile][2 nh][8 g][2 rh]
            float acc0 = 0.0f, acc1 = 0.0f;
#pragma unroll
            for (int ntl = 0; ntl < 4; ntl++) {
                int cc = (nh * 4 + ntl) * 8 + t * 2;
                float b0 = __ldg(projb + cc), b1 = __ldg(projb + cc + 1);
                float w0 = __ldg(outw + cc), w1 = __ldg(outw + cc + 1);
                acc0 += (c[ntl][0] + b0) * w0 + (c[ntl][1] + b1) * w1;
                acc1 += (c[ntl][2] + b0) * w0 + (c[ntl][3] + b1) * w1;
            }
            acc0 += __shfl_xor_sync(0xffffffff, acc0, 1);
            acc0 += __shfl_xor_sync(0xffffffff, acc0, 2);
            acc1 += __shfl_xor_sync(0xffffffff, acc1, 1);
            acc1 += __shfl_xor_sync(0xffffffff, acc1, 2);
            if (t == 0) {
                s_red[((mtile * 2 + nh) * 8 + g) * 2 + 0] = acc0;
                s_red[((mtile * 2 + nh) * 8 + g) * 2 + 1] = acc1;
            }
            __syncthreads();
            if (tid < 64) {
                int mt2 = tid >> 4, g2 = (tid >> 1) & 7, rh2 = tid & 1;
                float v = s_red[((mt2 * 2 + 0) * 8 + g2) * 2 + rh2] +
                          s_red[((mt2 * 2 + 1) * 8 + g2) * 2 + rh2] + __ldg(outb);
                int tok = mt2 * 16 + g2 + rh2 * 8;
                int ty = tok >> 3, tx = tok & 7;
                int gy = wy * 8 + ty, gx = wx * 8 + tx;
                out[(b * 128 + gy) * 128 + gx] = v;
            }
        }
    }
}

// ---------------------------------------------------------------------------
// Layer 1 conv on mma.sync (round-10 version: full row, 512 thr, 2-stage B)
// ---------------------------------------------------------------------------
#define L1_A_OFF 0
#define L1_A_BYTES (390 * 128)
#define L1_B0 L1_A_BYTES
#define L1_B_BYTES (320 * 128)
#define L1_B1 (L1_B0 + L1_B_BYTES)
#define L1_SMEM_TOTAL (L1_B1 + L1_B_BYTES)   // 131840

__device__ __forceinline__ void l1_load_B(u32 sB, int tap, int tid) {
    if (tid < 320) {
        const __half* src = g_w1h + (size_t)(tap * 320 + tid) * 64;
        u32 row = tid * 128;
        u32 sw = (u32)((tid & 7) << 4);
#pragma unroll
        for (int i = 0; i < 8; i++)
            cp16(sB + ((row + i * 16) ^ sw), (const char*)src + i * 16);
    }
}

__global__ __launch_bounds__(512, 1) void layer1_tc(const float* __restrict__ cb) {
    extern __shared__ char smem[];
    u32 sb = smem_u32(smem);
    int tid = threadIdx.x, lane = tid & 31, warp = tid >> 5;
    int wm = warp & 3, wn = warp >> 2;
    int tile = blockIdx.x;
    int b = tile >> 7, y = tile & 127;

    if (tid < 390) {
        int rowIdx = tid / 130, col = tid % 130;
        const __half* src = g_h16 +
            ((size_t)((b * 130 + y + rowIdx) * 130 + col)) * 64;
        u32 row = (u32)tid * 128;
        u32 sw = (u32)((tid & 7) << 4);
#pragma unroll
        for (int i = 0; i < 8; i++)
            cp16(sb + L1_A_OFF + ((row + i * 16) ^ sw), (const char*)src + i * 16);
    }
    l1_load_B(sb + L1_B0, 0, tid);
    CPASYNC_COMMIT();
    CPASYNC_WAIT0();
    __syncthreads();

    float c[2][5][2][4];
#pragma unroll
    for (int mi = 0; mi < 2; mi++)
#pragma unroll
        for (int g5 = 0; g5 < 5; g5++)
#pragma unroll
            for (int nt = 0; nt < 2; nt++)
#pragma unroll
                for (int e = 0; e < 4; e++) c[mi][g5][nt][e] = 0.0f;

    int arow = wm * 32 + (lane & 7) + 8 * ((lane >> 3) & 1);
    u32 aklane = (u32)(16 * (lane >> 4));
    u32 bkl = (u32)(((lane >> 3) & 1) * 16);
    int bnrow_base = wn * 16 + ((lane >> 4) & 1) * 8 + (lane & 7);
    u32 bswz = (u32)((lane & 7) << 4);

#pragma unroll 1
    for (int tap = 0; tap < 9; tap++) {
        u32 Bb = sb + ((tap & 1) ? L1_B1 : L1_B0);
        if (tap < 8) {
            l1_load_B(sb + ((tap & 1) ? L1_B0 : L1_B1), tap + 1, tid);
            CPASYNC_COMMIT();
        }
        int dy = tap / 3, dx = tap % 3;
        int br0 = dy * 130 + arow + dx;
#pragma unroll
        for (int ks = 0; ks < 4; ks++) {
            u32 a[2][4];
#pragma unroll
            for (int mi = 0; mi < 2; mi++) {
                u32 br = (u32)(br0 + mi * 16);
                u32 off = br * 128 + (u32)(ks * 32) + aklane;
                ldsm4(a[mi], sb + L1_A_OFF + (off ^ ((br & 7) << 4)));
            }
#pragma unroll
            for (int g5 = 0; g5 < 5; g5++) {
                u32 bfr[4];
                u32 nrow = (u32)(g5 * 64 + bnrow_base);
                u32 off = nrow * 128 + (u32)(ks * 32) + bkl;
                ldsm4(bfr, Bb + (off ^ bswz));
#pragma unroll
                for (int mi = 0; mi < 2; mi++) {
                    mma16816(c[mi][g5][0], a[mi], bfr[0], bfr[1]);
                    mma16816(c[mi][g5][1], a[mi], bfr[2], bfr[3]);
                }
            }
        }
        if (tap < 8) { CPASYNC_WAIT0(); }
        __syncthreads();
    }

    int q = lane & 3, gr = lane >> 2;
    int ocB = wn * 16;
#pragma unroll
    for (int mi = 0; mi < 2; mi++) {
#pragma unroll
        for (int rh = 0; rh < 2; rh++) {
            int x = wm * 32 + mi * 16 + gr + rh * 8;
            float* orow = g_buf0 + ((size_t)((b * 128 + y) * 128 + x)) * 64;
#pragma unroll
            for (int nt = 0; nt < 2; nt++) {
#pragma unroll
                for (int e = 0; e < 2; e++) {
                    int oc = ocB + nt * 8 + q * 2 + e;
                    int ai = rh * 2 + e;
                    float ci = c[mi][0][nt][ai];
                    float co = c[mi][1][nt][ai];
                    float cg = c[mi][2][nt][ai];
                    float px = c[mi][3][nt][ai];
                    float py = c[mi][4][nt][ai];
                    float ig = sigm(ci + px + __ldg(cb + oc));
                    float og = sigm(co + py + __ldg(cb + 128 + oc));
                    float gg = ftanh(cg + py + __ldg(cb + 192 + oc));
                    orow[oc] = og * ftanh(ig * gg);
                }
            }
        }
    }
}

// ---------------------------------------------------------------------------
extern "C" void kernel_launch(void* const* d_in, const int* in_sizes, int n_in,
                              void* d_out, int out_size) {
    const float* x      = (const float*)d_in[0];
    const float* cw0    = (const float*)d_in[1];
    const float* cb0    = (const float*)d_in[2];
    const float* pxw0   = (const float*)d_in[3];
    const float* pyw0   = (const float*)d_in[4];
    const float* qkvw0  = (const float*)d_in[5];
    const float* projw0 = (const float*)d_in[6];
    const float* projb0 = (const float*)d_in[7];
    const float* cw1    = (const float*)d_in[8];
    const float* cb1    = (const float*)d_in[9];
    const float* pxw1   = (const float*)d_in[10];
    const float* pyw1   = (const float*)d_in[11];
    const float* qkvw1  = (const float*)d_in[12];
    const float* projw1 = (const float*)d_in[13];
    const float* projb1 = (const float*)d_in[14];
    const float* outw   = (const float*)d_in[15];
    const float* outb   = (const float*)d_in[16];
    float* out = (float*)d_out;

    cudaFuncSetAttribute(win_attn_tc, cudaFuncAttributeMaxDynamicSharedMemorySize,
                         AT_SMEM);
    cudaFuncSetAttribute(layer1_tc, cudaFuncAttributeMaxDynamicSharedMemorySize,
                         L1_SMEM_TOTAL);

    prep_all<<<(PREP_TOTAL + 255) / 256, 256>>>(cw1, pxw1, pyw1,
                                                qkvw0, projw0, qkvw1, projw1);
    // fused layer0 + attention pass 0: x -> h16
    win_attn_tc<<<4096, 256, AT_SMEM>>>(0, projb0, outw, outb, out, 1,
                                        x, cw0, cb0, pxw0, pyw0, 1);
    layer1_tc<<<2048, 512, L1_SMEM_TOTAL>>>(cb1);                     // h16 -> buf0
    // attention pass 1 + fused output conv: buf0 -> out
    win_attn_tc<<<4096, 256, AT_SMEM>>>(1, projb1, outw, outb, out, 0,
                                        x, cw0, cb0, pxw0, pyw0, 0);
}

// round 14
// speedup vs baseline: 1.1842x; 1.1842x over previous
#include <cuda_runtime.h>
#include <cuda_fp16.h>
#include <math.h>
#include <stdint.h>

#define BATCH 16
#define HDIM 128
#define WDIM 128
#define HID 64

typedef uint32_t u32;
typedef uint16_t u16;

// layer-0 output h (NHWC fp32); consumed by attention pass 0; reused for h1
__device__ __align__(16) float g_buf0[BATCH * HDIM * WDIM * HID];
// padded f16 activations for layer-1 conv: [16][130][130][64]
__device__ __align__(16) __half g_h16[BATCH * 130 * 130 * HID];
// f16 layer-1 weights: [tap 9][gate*64+oc 320][cin 64]
__device__ __align__(16) __half g_w1h[9 * 320 * 64];
// f16 attention weights hi/lo (Markidis split): per layer qkv [192][64], proj [64][64]
__device__ __align__(16) __half g_wqh[2][192 * 64];
__device__ __align__(16) __half g_wql[2][192 * 64];
__device__ __align__(16) __half g_wph[2][64 * 64];
__device__ __align__(16) __half g_wpl[2][64 * 64];

__device__ __forceinline__ float sigm(float v) {
    return __fdividef(1.0f, 1.0f + __expf(-v));
}
__device__ __forceinline__ float ftanh(float v) {
    return 1.0f - __fdividef(2.0f, __expf(2.0f * v) + 1.0f);
}

// ===================== sm_80+ tensor helpers (no 'a' target) ================
__device__ __forceinline__ u32 smem_u32(const void* p) {
    u32 a;
    asm("{ .reg .u64 t; cvta.to.shared.u64 t, %1; cvt.u32.u64 %0, t; }"
        : "=r"(a) : "l"(p));
    return a;
}
__device__ __forceinline__ void cp16(u32 dst, const void* src) {
    asm volatile("cp.async.cg.shared.global [%0], [%1], 16;" :: "r"(dst), "l"(src));
}
#define CPASYNC_COMMIT() asm volatile("cp.async.commit_group;" ::: "memory")
#define CPASYNC_WAIT0()  asm volatile("cp.async.wait_group 0;" ::: "memory")

__device__ __forceinline__ void ldsm4(u32* r, u32 a) {
    asm volatile("ldmatrix.sync.aligned.m8n8.x4.shared.b16 {%0,%1,%2,%3}, [%4];"
                 : "=r"(r[0]), "=r"(r[1]), "=r"(r[2]), "=r"(r[3]) : "r"(a));
}
__device__ __forceinline__ void mma16816(float* c, const u32* a, u32 b0, u32 b1) {
    asm volatile(
        "mma.sync.aligned.m16n8k16.row.col.f32.f16.f16.f32 "
        "{%0,%1,%2,%3}, {%4,%5,%6,%7}, {%8,%9}, {%0,%1,%2,%3};"
        : "+f"(c[0]), "+f"(c[1]), "+f"(c[2]), "+f"(c[3])
        : "r"(a[0]), "r"(a[1]), "r"(a[2]), "r"(a[3]), "r"(b0), "r"(b1));
}
__device__ __forceinline__ u32 pk2(float lo, float hi) {   // {lo | hi<<16}
    u32 r;
    asm("cvt.rn.f16x2.f32 %0, %1, %2;" : "=r"(r) : "f"(hi), "f"(lo));
    return r;
}
// f16 hi/lo split of a float pair
__device__ __forceinline__ void split2(float a, float b, u32& hi, u32& lo) {
    __half ha = __float2half_rn(a), hb = __float2half_rn(b);
    hi = ((u32)__half_as_ushort(hb) << 16) | (u32)__half_as_ushort(ha);
    lo = pk2(a - __half2float(ha), b - __half2float(hb));
}
__device__ __forceinline__ void sts32(u32 addr, u32 v) {
    asm volatile("st.shared.b32 [%0], %1;" :: "r"(addr), "r"(v));
}
__device__ __forceinline__ void sts16(u32 addr, float v) {
    u16 b = __half_as_ushort(__float2half_rn(v));
    asm volatile("st.shared.b16 [%0], %1;" :: "r"(addr), "h"(b) : "memory");
}

// ---------------------------------------------------------------------------
// Prep work sizes (executed by extra blocks of the layer0 launch)
// ---------------------------------------------------------------------------
#define PREP_A (9 * 320 * 64)          // 184320
#define PREP_B (BATCH * 130 * 130)     // 270400
#define PREP_C (192 * 64)              // 12288
#define PREP_D (64 * 64)               // 4096
#define PREP_TOTAL (PREP_A + PREP_B + PREP_C + PREP_D)
#define PREP_BLOCKS ((PREP_TOTAL + 255) / 256)

__device__ __forceinline__ void do_prep(
    int idx,
    const float* __restrict__ cw, const float* __restrict__ pxw,
    const float* __restrict__ pyw,
    const float* __restrict__ q0, const float* __restrict__ p0,
    const float* __restrict__ q1, const float* __restrict__ p1) {
    if (idx < PREP_A) {
        int tap = idx / (320 * 64);
        int rem = idx % (320 * 64);
        int r = rem / 64, cin = rem % 64;
        int g = r >> 6, n = r & 63;
        float v;
        if (g == 0)      v = cw[(n * 128 + cin) * 9 + tap];
        else if (g == 1) v = cw[((128 + n) * 128 + cin) * 9 + tap];
        else if (g == 2) v = cw[((192 + n) * 128 + cin) * 9 + tap];
        else if (g == 3) v = pxw[(n * 64 + cin) * 9 + tap];
        else             v = pyw[(n * 64 + cin) * 9 + tap];
        g_w1h[idx] = __float2half_rn(v);
        return;
    }
    idx -= PREP_A;
    if (idx < PREP_B) {
        int bp = idx % (130 * 130);
        int yy = bp / 130, xx = bp % 130;
        if (yy == 0 || yy == 129 || xx == 0 || xx == 129) {
            uint4* d = (uint4*)(g_h16 + (size_t)idx * 64);
            uint4 z = {0, 0, 0, 0};
#pragma unroll
            for (int i = 0; i < 8; i++) d[i] = z;
        }
        return;
    }
    idx -= PREP_B;
    if (idx < PREP_C) {
        float v0 = q0[idx], v1 = q1[idx];
        __half h0 = __float2half_rn(v0), h1 = __float2half_rn(v1);
        g_wqh[0][idx] = h0; g_wql[0][idx] = __float2half_rn(v0 - __half2float(h0));
        g_wqh[1][idx] = h1; g_wql[1][idx] = __float2half_rn(v1 - __half2float(h1));
        return;
    }
    idx -= PREP_C;
    if (idx < PREP_D) {
        float v0 = p0[idx], v1 = p1[idx];
        __half h0 = __float2half_rn(v0), h1 = __float2half_rn(v1);
        g_wph[0][idx] = h0; g_wpl[0][idx] = __float2half_rn(v0 - __half2float(h0));
        g_wph[1][idx] = h1; g_wpl[1][idx] = __float2half_rn(v1 - __half2float(h1));
    }
}

// ---------------------------------------------------------------------------
// Layer 0 fused gates (round-10 version) + prep piggyback blocks.
// Blocks [0,1024): layer-0 pixels. Blocks >= 1024: prep work, then exit.
// ---------------------------------------------------------------------------
__global__ __launch_bounds__(256) void layer0_gates(
    const float* __restrict__ x, const float* __restrict__ cw,
    const float* __restrict__ cb, const float* __restrict__ pxw,
    const float* __restrict__ pyw,
    const float* __restrict__ cw1, const float* __restrict__ pxw1,
    const float* __restrict__ pyw1,
    const float* __restrict__ q0, const float* __restrict__ p0,
    const float* __restrict__ q1, const float* __restrict__ p1) {
    __shared__ float s_w[64 * 48];
    __shared__ float s_b[3][64];
    __shared__ float s_out[256 * 20];
    int tid = threadIdx.x;

    if (blockIdx.x >= 1024) {
        int idx = (blockIdx.x - 1024) * 256 + tid;
        do_prep(idx, cw1, pxw1, pyw1, q0, p0, q1, p1);
        return;
    }

    for (int i = tid; i < 64 * 45; i += 256) {
        int c = i / 45, j = i % 45;
        int g = j / 9, tap = j % 9;
        float v;
        if (g == 0)      v = cw[c * 585 + tap];
        else if (g == 1) v = cw[(128 + c) * 585 + tap];
        else if (g == 2) v = cw[(192 + c) * 585 + tap];
        else if (g == 3) v = pxw[c * 9 + tap];
        else             v = pyw[c * 9 + tap];
        s_w[c * 48 + j] = v;
    }
    if (tid < 64) {
        s_b[0][tid] = cb[tid];
        s_b[1][tid] = cb[128 + tid];
        s_b[2][tid] = cb[192 + tid];
    }
    __syncthreads();

    int p = blockIdx.x * 256 + tid;
    int b = p >> 14, y = (p >> 7) & 127, xc = p & 127;
    float pv[9];
#pragma unroll
    for (int ky = 0; ky < 3; ky++)
#pragma unroll
        for (int kx = 0; kx < 3; kx++) {
            int gy = y + ky - 1, gx = xc + kx - 1;
            pv[ky * 3 + kx] = (gy >= 0 && gy < 128 && gx >= 0 && gx < 128)
                                  ? x[(b << 14) + gy * 128 + gx] : 0.0f;
        }

#pragma unroll 1
    for (int chunk = 0; chunk < 4; chunk++) {
        float4 ov;
#pragma unroll
        for (int cc = 0; cc < 16; cc++) {
            int c = chunk * 16 + cc;
            float wv[48];
            const float4* w4 = (const float4*)(s_w + c * 48);
#pragma unroll
            for (int q = 0; q < 12; q++) {
                float4 t4 = w4[q];
                wv[q * 4 + 0] = t4.x; wv[q * 4 + 1] = t4.y;
                wv[q * 4 + 2] = t4.z; wv[q * 4 + 3] = t4.w;
            }
            float aci = 0.f, aco = 0.f, acg = 0.f, apx = 0.f, apy = 0.f;
#pragma unroll
            for (int tap = 0; tap < 9; tap++) {
                float a = pv[tap];
                aci += a * wv[tap];
                aco += a * wv[9 + tap];
                acg += a * wv[18 + tap];
                apx += a * wv[27 + tap];
                apy += a * wv[36 + tap];
            }
            float ig = sigm(aci + apx + s_b[0][c]);
            float og = sigm(aco + apy + s_b[1][c]);
            float gg = ftanh(acg + apy + s_b[2][c]);
            float r = og * ftanh(ig * gg);
            int e = cc & 3;
            if (e == 0) ov.x = r; else if (e == 1) ov.y = r;
            else if (e == 2) ov.z = r;
            else {
                ov.w = r;
                *(float4*)(s_out + tid * 20 + (cc >> 2) * 4) = ov;
            }
        }
        __syncthreads();
#pragma unroll
        for (int it = 0; it < 4; it++) {
            int i = it * 256 + tid;
            int pp = i >> 2, k = i & 3;
            float4 v4 = *(const float4*)(s_out + pp * 20 + k * 4);
            *(float4*)(g_buf0 +
                       ((size_t)(blockIdx.x * 256 + pp)) * 64 + chunk * 16 + k * 4) = v4;
        }
        __syncthreads();
    }
}

// ---------------------------------------------------------------------------
// Window attention on mma.sync with f16 hi/lo compensation, 8 warps/window.
// (round-10 version, byte-identical)
// ---------------------------------------------------------------------------
#define AT_XH 0
#define AT_XL 8192
#define AT_QH 16384
#define AT_QL 24576
#define AT_KH 32768
#define AT_KL 40960
#define AT_VTH 49152
#define AT_VTL 57344
#define AT_WQH 65536
#define AT_WQL 90112
#define AT_RED 114688
#define AT_SMEM 115200

__global__ __launch_bounds__(256, 2) void win_attn_tc(
    int layer, const float* __restrict__ projb,
    const float* __restrict__ outw, const float* __restrict__ outb,
    float* __restrict__ out, int to_h16) {
    extern __shared__ char smem[];
    u32 sb = smem_u32(smem);
    int tid = threadIdx.x, lane = tid & 31, w = tid >> 5;
    int wid = blockIdx.x;
    int b = wid >> 8, wy = (wid >> 4) & 15, wx = wid & 15;
    int base = ((b * 128 + wy * 8) * 128 + wx * 8) * 64;

    // ---- stage qkv weights hi/lo ----
    if (tid < 192) {
        int r = tid;
        const __half* sh = g_wqh[layer] + r * 64;
        const __half* sl = g_wql[layer] + r * 64;
        u32 row = (u32)r * 128, sw = (u32)((r & 7) << 4);
#pragma unroll
        for (int i = 0; i < 8; i++) {
            cp16(sb + AT_WQH + ((row + i * 16) ^ sw), (const char*)sh + i * 16);
            cp16(sb + AT_WQL + ((row + i * 16) ^ sw), (const char*)sl + i * 16);
        }
    }
    CPASYNC_COMMIT();
    {
        int row = tid >> 2, q = tid & 3;              // token row, 16-col quarter
        int ty = row >> 3, tx = row & 7;
        const float* src = g_buf0 + base + (ty * 128 + tx) * 64 + q * 16;
        u32 sw = (u32)((row & 7) << 4);
#pragma unroll
        for (int j = 0; j < 4; j++) {
            float4 a = *(const float4*)(src + j * 4);
            u32 byte0 = (u32)(row * 128 + q * 32 + j * 8);
            u32 h01, l01, h23, l23;
            split2(a.x, a.y, h01, l01);
            split2(a.z, a.w, h23, l23);
            sts32(sb + AT_XH + (byte0 ^ sw), h01);
            sts32(sb + AT_XL + (byte0 ^ sw), l01);
            sts32(sb + AT_XH + ((byte0 + 4) ^ sw), h23);
            sts32(sb + AT_XL + ((byte0 + 4) ^ sw), l23);
        }
    }
    CPASYNC_WAIT0();
    __syncthreads();

    // lane-invariant ldsm address pieces
    int aRow = (lane & 7) + 8 * ((lane >> 3) & 1);
    u32 aKl = (u32)(16 * (lane >> 4));
    int bRow = ((lane >> 4) & 1) * 8 + (lane & 7);
    u32 bKl = (u32)(((lane >> 3) & 1) * 16);
    int g = lane >> 2, t = lane & 3;

    // ---- phase 1: QKV GEMM (3-term). warp = (ocg, mh) ----
    {
        int ocg = w >> 1, mh = w & 1;
        float c[2][6][4];
#pragma unroll
        for (int mtl = 0; mtl < 2; mtl++)
#pragma unroll
            for (int nt = 0; nt < 6; nt++)
#pragma unroll
                for (int e = 0; e < 4; e++) c[mtl][nt][e] = 0.0f;

#pragma unroll
        for (int ks = 0; ks < 4; ks++) {
            u32 ah[2][4], al[2][4];
#pragma unroll
            for (int mtl = 0; mtl < 2; mtl++) {
                u32 ar = (u32)((mh * 2 + mtl) * 16 + aRow);
                u32 off = ar * 128 + (u32)(ks * 32) + aKl;
                u32 sw = ((ar & 7) << 4);
                ldsm4(ah[mtl], sb + AT_XH + (off ^ sw));
                ldsm4(al[mtl], sb + AT_XL + (off ^ sw));
            }
#pragma unroll
            for (int np = 0; np < 3; np++) {
                u32 bh[4], bl[4];
                u32 nr = (u32)(ocg * 48 + np * 16 + bRow);
                u32 off = nr * 128 + (u32)(ks * 32) + bKl;
                u32 sw = ((nr & 7) << 4);
                ldsm4(bh, sb + AT_WQH + (off ^ sw));
                ldsm4(bl, sb + AT_WQL + (off ^ sw));
#pragma unroll
                for (int mtl = 0; mtl < 2; mtl++) {
                    mma16816(c[mtl][np * 2], ah[mtl], bh[0], bh[1]);
                    mma16816(c[mtl][np * 2], al[mtl], bh[0], bh[1]);
                    mma16816(c[mtl][np * 2], ah[mtl], bl[0], bl[1]);
                    mma16816(c[mtl][np * 2 + 1], ah[mtl], bh[2], bh[3]);
                    mma16816(c[mtl][np * 2 + 1], al[mtl], bh[2], bh[3]);
                    mma16816(c[mtl][np * 2 + 1], ah[mtl], bl[2], bl[3]);
                }
            }
        }
        // store Q (x0.25), K, V^T as f16 hi/lo
#pragma unroll
        for (int mtl = 0; mtl < 2; mtl++) {
            int mt = (w & 1) * 2 + mtl;
#pragma unroll
            for (int nt = 0; nt < 6; nt++) {
                int nc = ocg * 48 + nt * 8 + t * 2;
                int r0 = mt * 16 + g, r1 = r0 + 8;
                float v0 = c[mtl][nt][0], v1 = c[mtl][nt][1];
                float v2 = c[mtl][nt][2], v3 = c[mtl][nt][3];
                u32 sw0 = ((u32)(r0 & 7) << 4), sw1 = ((u32)(r1 & 7) << 4);
                if (nc < 64) {
                    u32 h01, l01, h23, l23;
                    split2(v0 * 0.25f, v1 * 0.25f, h01, l01);
                    split2(v2 * 0.25f, v3 * 0.25f, h23, l23);
                    u32 o0 = ((u32)(r0 * 128 + nc * 2)) ^ sw0;
                    u32 o1 = ((u32)(r1 * 128 + nc * 2)) ^ sw1;
                    sts32(sb + AT_QH + o0, h01); sts32(sb + AT_QL + o0, l01);
                    sts32(sb + AT_QH + o1, h23); sts32(sb + AT_QL + o1, l23);
                } else if (nc < 128) {
                    int kc = nc - 64;
                    u32 h01, l01, h23, l23;
                    split2(v0, v1, h01, l01);
                    split2(v2, v3, h23, l23);
                    u32 o0 = ((u32)(r0 * 128 + kc * 2)) ^ sw0;
                    u32 o1 = ((u32)(r1 * 128 + kc * 2)) ^ sw1;
                    sts32(sb + AT_KH + o0, h01); sts32(sb + AT_KL + o0, l01);
                    sts32(sb + AT_KH + o1, h23); sts32(sb + AT_KL + o1, l23);
                } else {
                    int d0 = nc - 128, d1 = d0 + 1;
                    u32 s0 = (u32)((d0 & 7) << 4), s1 = (u32)((d1 & 7) << 4);
                    float vv[4] = {v0, v1, v2, v3};
                    int dd[4] = {d0, d1, d0, d1};
                    int rr[4] = {r0, r0, r1, r1};
                    u32 ss[4] = {s0, s1, s0, s1};
#pragma unroll
                    for (int e = 0; e < 4; e++) {
                        __half h = __float2half_rn(vv[e]);
                        float rl = vv[e] - __half2float(h);
                        u32 off = ((u32)(dd[e] * 128 + rr[e] * 2)) ^ ss[e];
                        sts16(sb + AT_VTH + off, vv[e]);
                        sts16(sb + AT_VTL + off, rl);
                    }
                }
            }
        }
    }
    __syncthreads();

    // ---- phase 2: attention, warp = (head, mt-half) ----
    {
        int h = w >> 1, mh = w & 1;
        u32 kbh[4][4], kbl[4][4], vbh[4][4], vbl[4][4];
#pragma unroll
        for (int np = 0; np < 4; np++) {
            u32 nr = (u32)(np * 16 + bRow);
            u32 off = nr * 128 + (u32)(h * 32) + bKl;
            u32 sw = ((nr & 7) << 4);
            ldsm4(kbh[np], sb + AT_KH + (off ^ sw));
            ldsm4(kbl[np], sb + AT_KL + (off ^ sw));
        }
#pragma unroll
        for (int ks = 0; ks < 4; ks++) {
            u32 nr = (u32)(h * 16 + bRow);
            u32 off = nr * 128 + (u32)(ks * 32) + bKl;
            u32 sw = ((nr & 7) << 4);
            ldsm4(vbh[ks], sb + AT_VTH + (off ^ sw));
            ldsm4(vbl[ks], sb + AT_VTL + (off ^ sw));
        }
        __syncthreads();   // all warps hold K/V fragments; vt planes now free
        // stage proj weights into the vt planes (overlap with compute)
        if (tid < 128) {
            int r = tid & 63;
            const __half* src = (tid < 64) ? (g_wph[layer] + r * 64)
                                           : (g_wpl[layer] + r * 64);
            u32 dstb = (tid < 64) ? (sb + AT_VTH) : (sb + AT_VTL);
            u32 row = (u32)r * 128, sw = (u32)((r & 7) << 4);
#pragma unroll
            for (int i = 0; i < 8; i++)
                cp16(dstb + ((row + i * 16) ^ sw), (const char*)src + i * 16);
        }
        CPASYNC_COMMIT();

#pragma unroll
        for (int mtl = 0; mtl < 2; mtl++) {
            int mt = mh * 2 + mtl;
            u32 aqh[4], aql[4];
            u32 ar = (u32)(mt * 16 + aRow);
            u32 off = ar * 128 + (u32)(h * 32) + aKl;
            u32 sw = ((ar & 7) << 4);
            ldsm4(aqh, sb + AT_QH + (off ^ sw));
            ldsm4(aql, sb + AT_QL + (off ^ sw));

            float s[8][4];
#pragma unroll
            for (int nt = 0; nt < 8; nt++)
#pragma unroll
                for (int e = 0; e < 4; e++) s[nt][e] = 0.0f;
#pragma unroll
            for (int np = 0; np < 4; np++) {
                mma16816(s[np * 2], aqh, kbh[np][0], kbh[np][1]);
                mma16816(s[np * 2], aql, kbh[np][0], kbh[np][1]);
                mma16816(s[np * 2], aqh, kbl[np][0], kbl[np][1]);
                mma16816(s[np * 2 + 1], aqh, kbh[np][2], kbh[np][3]);
                mma16816(s[np * 2 + 1], aql, kbh[np][2], kbh[np][3]);
                mma16816(s[np * 2 + 1], aqh, kbl[np][2], kbl[np][3]);
            }
            // softmax rows (mt*16+g) and (+8)
            float m0 = -1e30f, m1 = -1e30f;
#pragma unroll
            for (int nt = 0; nt < 8; nt++) {
                m0 = fmaxf(m0, fmaxf(s[nt][0], s[nt][1]));
                m1 = fmaxf(m1, fmaxf(s[nt][2], s[nt][3]));
            }
            m0 = fmaxf(m0, __shfl_xor_sync(0xffffffff, m0, 1));
            m0 = fmaxf(m0, __shfl_xor_sync(0xffffffff, m0, 2));
            m1 = fmaxf(m1, __shfl_xor_sync(0xffffffff, m1, 1));
            m1 = fmaxf(m1, __shfl_xor_sync(0xffffffff, m1, 2));
            float s0 = 0.f, s1 = 0.f;
#pragma unroll
            for (int nt = 0; nt < 8; nt++) {
                s[nt][0] = __expf(s[nt][0] - m0); s0 += s[nt][0];
                s[nt][1] = __expf(s[nt][1] - m0); s0 += s[nt][1];
                s[nt][2] = __expf(s[nt][2] - m1); s1 += s[nt][2];
                s[nt][3] = __expf(s[nt][3] - m1); s1 += s[nt][3];
            }
            s0 += __shfl_xor_sync(0xffffffff, s0, 1);
            s0 += __shfl_xor_sync(0xffffffff, s0, 2);
            s1 += __shfl_xor_sync(0xffffffff, s1, 1);
            s1 += __shfl_xor_sync(0xffffffff, s1, 2);
            float i0 = 1.0f / s0, i1 = 1.0f / s1;

            float o[2][4];
#pragma unroll
            for (int nt = 0; nt < 2; nt++)
#pragma unroll
                for (int e = 0; e < 4; e++) o[nt][e] = 0.0f;
#pragma unroll
            for (int ks = 0; ks < 4; ks++) {
                u32 ph[4], pl[4];
                split2(s[2 * ks][0], s[2 * ks][1], ph[0], pl[0]);
                split2(s[2 * ks][2], s[2 * ks][3], ph[1], pl[1]);
                split2(s[2 * ks + 1][0], s[2 * ks + 1][1], ph[2], pl[2]);
                split2(s[2 * ks + 1][2], s[2 * ks + 1][3], ph[3], pl[3]);
                mma16816(o[0], ph, vbh[ks][0], vbh[ks][1]);
                mma16816(o[0], pl, vbh[ks][0], vbh[ks][1]);
                mma16816(o[0], ph, vbl[ks][0], vbl[ks][1]);
                mma16816(o[1], ph, vbh[ks][2], vbh[ks][3]);
                mma16816(o[1], pl, vbh[ks][2], vbh[ks][3]);
                mma16816(o[1], ph, vbl[ks][2], vbl[ks][3]);
            }
            // scale + store O hi/lo to x planes
            int r0 = mt * 16 + g, r1 = r0 + 8;
            u32 sw0 = ((u32)(r0 & 7) << 4), sw1 = ((u32)(r1 & 7) << 4);
#pragma unroll
            for (int nt = 0; nt < 2; nt++) {
                int dc = h * 16 + nt * 8 + t * 2;
                u32 h01, l01, h23, l23;
                split2(o[nt][0] * i0, o[nt][1] * i0, h01, l01);
                split2(o[nt][2] * i1, o[nt][3] * i1, h23, l23);
                u32 o0 = ((u32)(r0 * 128 + dc * 2)) ^ sw0;
                u32 o1 = ((u32)(r1 * 128 + dc * 2)) ^ sw1;
                sts32(sb + AT_XH + o0, h01); sts32(sb + AT_XL + o0, l01);
                sts32(sb + AT_XH + o1, h23); sts32(sb + AT_XL + o1, l23);
            }
        }
    }
    CPASYNC_WAIT0();
    __syncthreads();

    // ---- phase 3: proj GEMM (3-term), warp = (m-tile, n-half) ----
    {
        int mtile = w >> 1, nh = w & 1;
        float c[4][4];
#pragma unroll
        for (int nt = 0; nt < 4; nt++)
#pragma unroll
            for (int e = 0; e < 4; e++) c[nt][e] = 0.0f;
#pragma unroll
        for (int ks = 0; ks < 4; ks++) {
            u32 ah[4], al[4];
            u32 ar = (u32)(mtile * 16 + aRow);
            u32 off = ar * 128 + (u32)(ks * 32) + aKl;
            u32 sw = ((ar & 7) << 4);
            ldsm4(ah, sb + AT_XH + (off ^ sw));
            ldsm4(al, sb + AT_XL + (off ^ sw));
#pragma unroll
            for (int npl = 0; npl < 2; npl++) {
                int np = nh * 2 + npl;
                u32 bh[4], bl[4];
                u32 nr = (u32)(np * 16 + bRow);
                u32 boff = nr * 128 + (u32)(ks * 32) + bKl;
                u32 bsw = ((nr & 7) << 4);
                ldsm4(bh, sb + AT_VTH + (boff ^ bsw));
                ldsm4(bl, sb + AT_VTL + (boff ^ bsw));
                mma16816(c[npl * 2], ah, bh[0], bh[1]);
                mma16816(c[npl * 2], al, bh[0], bh[1]);
                mma16816(c[npl * 2], ah, bl[0], bl[1]);
                mma16816(c[npl * 2 + 1], ah, bh[2], bh[3]);
                mma16816(c[npl * 2 + 1], al, bh[2], bh[3]);
                mma16816(c[npl * 2 + 1], ah, bl[2], bl[3]);
            }
        }
        if (to_h16) {
#pragma unroll
            for (int ntl = 0; ntl < 4; ntl++) {
                int nt = nh * 4 + ntl;
                int cc = nt * 8 + t * 2;
                float b0 = __ldg(projb + cc), b1 = __ldg(projb + cc + 1);
#pragma unroll
                for (int rh = 0; rh < 2; rh++) {
                    int tok = mtile * 16 + g + rh * 8;
                    int ty = tok >> 3, tx = tok & 7;
                    float v0 = c[ntl][rh * 2] + b0, v1 = c[ntl][rh * 2 + 1] + b1;
                    int gy = wy * 8 + ty, gx = wx * 8 + tx;
                    __half* dst = g_h16 +
                        ((size_t)((b * 130 + gy + 1) * 130 + gx + 1)) * 64 + cc;
                    *(__half2*)dst = __floats2half2_rn(v0, v1);
                }
            }
        } else {
            float* s_red = (float*)(smem + AT_RED);    // [4 mtile][2 nh][8 g][2 rh]
            float acc0 = 0.0f, acc1 = 0.0f;
#pragma unroll
            for (int ntl = 0; ntl < 4; ntl++) {
                int cc = (nh * 4 + ntl) * 8 + t * 2;
                float b0 = __ldg(projb + cc), b1 = __ldg(projb + cc + 1);
                float w0 = __ldg(outw + cc), w1 = __ldg(outw + cc + 1);
                acc0 += (c[ntl][0] + b0) * w0 + (c[ntl][1] + b1) * w1;
                acc1 += (c[ntl][2] + b0) * w0 + (c[ntl][3] + b1) * w1;
            }
            acc0 += __shfl_xor_sync(0xffffffff, acc0, 1);
            acc0 += __shfl_xor_sync(0xffffffff, acc0, 2);
            acc1 += __shfl_xor_sync(0xffffffff, acc1, 1);
            acc1 += __shfl_xor_sync(0xffffffff, acc1, 2);
            if (t == 0) {
                s_red[((mtile * 2 + nh) * 8 + g) * 2 + 0] = acc0;
                s_red[((mtile * 2 + nh) * 8 + g) * 2 + 1] = acc1;
            }
            __syncthreads();
            if (tid < 64) {
                int mt2 = tid >> 4, g2 = (tid >> 1) & 7, rh2 = tid & 1;
                float v = s_red[((mt2 * 2 + 0) * 8 + g2) * 2 + rh2] +
                          s_red[((mt2 * 2 + 1) * 8 + g2) * 2 + rh2] + __ldg(outb);
                int tok = mt2 * 16 + g2 + rh2 * 8;
                int ty = tok >> 3, tx = tok & 7;
                int gy = wy * 8 + ty, gx = wx * 8 + tx;
                out[(b * 128 + gy) * 128 + gx] = v;
            }
        }
    }
}

// ---------------------------------------------------------------------------
// Layer 1 conv on mma.sync (round-10 version: full row, 512 thr, 2-stage B)
// ---------------------------------------------------------------------------
#define L1_A_OFF 0
#define L1_A_BYTES (390 * 128)
#define L1_B0 L1_A_BYTES
#define L1_B_BYTES (320 * 128)
#define L1_B1 (L1_B0 + L1_B_BYTES)
#define L1_SMEM_TOTAL (L1_B1 + L1_B_BYTES)   // 131840

__device__ __forceinline__ void l1_load_B(u32 sB, int tap, int tid) {
    if (tid < 320) {
        const __half* src = g_w1h + (size_t)(tap * 320 + tid) * 64;
        u32 row = tid * 128;
        u32 sw = (u32)((tid & 7) << 4);
#pragma unroll
        for (int i = 0; i < 8; i++)
            cp16(sB + ((row + i * 16) ^ sw), (const char*)src + i * 16);
    }
}

__global__ __launch_bounds__(512, 1) void layer1_tc(const float* __restrict__ cb) {
    extern __shared__ char smem[];
    u32 sb = smem_u32(smem);
    int tid = threadIdx.x, lane = tid & 31, warp = tid >> 5;
    int wm = warp & 3, wn = warp >> 2;
    int tile = blockIdx.x;
    int b = tile >> 7, y = tile & 127;

    if (tid < 390) {
        int rowIdx = tid / 130, col = tid % 130;
        const __half* src = g_h16 +
            ((size_t)((b * 130 + y + rowIdx) * 130 + col)) * 64;
        u32 row = (u32)tid * 128;
        u32 sw = (u32)((tid & 7) << 4);
#pragma unroll
        for (int i = 0; i < 8; i++)
            cp16(sb + L1_A_OFF + ((row + i * 16) ^ sw), (const char*)src + i * 16);
    }
    l1_load_B(sb + L1_B0, 0, tid);
    CPASYNC_COMMIT();
    CPASYNC_WAIT0();
    __syncthreads();

    float c[2][5][2][4];
#pragma unroll
    for (int mi = 0; mi < 2; mi++)
#pragma unroll
        for (int g5 = 0; g5 < 5; g5++)
#pragma unroll
            for (int nt = 0; nt < 2; nt++)
#pragma unroll
                for (int e = 0; e < 4; e++) c[mi][g5][nt][e] = 0.0f;

    int arow = wm * 32 + (lane & 7) + 8 * ((lane >> 3) & 1);
    u32 aklane = (u32)(16 * (lane >> 4));
    u32 bkl = (u32)(((lane >> 3) & 1) * 16);
    int bnrow_base = wn * 16 + ((lane >> 4) & 1) * 8 + (lane & 7);
    u32 bswz = (u32)((lane & 7) << 4);

#pragma unroll 1
    for (int tap = 0; tap < 9; tap++) {
        u32 Bb = sb + ((tap & 1) ? L1_B1 : L1_B0);
        if (tap < 8) {
            l1_load_B(sb + ((tap & 1) ? L1_B0 : L1_B1), tap + 1, tid);
            CPASYNC_COMMIT();
        }
        int dy = tap / 3, dx = tap % 3;
        int br0 = dy * 130 + arow + dx;
#pragma unroll
        for (int ks = 0; ks < 4; ks++) {
            u32 a[2][4];
#pragma unroll
            for (int mi = 0; mi < 2; mi++) {
                u32 br = (u32)(br0 + mi * 16);
                u32 off = br * 128 + (u32)(ks * 32) + aklane;
                ldsm4(a[mi], sb + L1_A_OFF + (off ^ ((br & 7) << 4)));
            }
#pragma unroll
            for (int g5 = 0; g5 < 5; g5++) {
                u32 bfr[4];
                u32 nrow = (u32)(g5 * 64 + bnrow_base);
                u32 off = nrow * 128 + (u32)(ks * 32) + bkl;
                ldsm4(bfr, Bb + (off ^ bswz));
#pragma unroll
                for (int mi = 0; mi < 2; mi++) {
                    mma16816(c[mi][g5][0], a[mi], bfr[0], bfr[1]);
                    mma16816(c[mi][g5][1], a[mi], bfr[2], bfr[3]);
                }
            }
        }
        if (tap < 8) { CPASYNC_WAIT0(); }
        __syncthreads();
    }

    int q = lane & 3, gr = lane >> 2;
    int ocB = wn * 16;
#pragma unroll
    for (int mi = 0; mi < 2; mi++) {
#pragma unroll
        for (int rh = 0; rh < 2; rh++) {
            int x = wm * 32 + mi * 16 + gr + rh * 8;
            float* orow = g_buf0 + ((size_t)((b * 128 + y) * 128 + x)) * 64;
#pragma unroll
            for (int nt = 0; nt < 2; nt++) {
#pragma unroll
                for (int e = 0; e < 2; e++) {
                    int oc = ocB + nt * 8 + q * 2 + e;
                    int ai = rh * 2 + e;
                    float ci = c[mi][0][nt][ai];
                    float co = c[mi][1][nt][ai];
                    float cg = c[mi][2][nt][ai];
                    float px = c[mi][3][nt][ai];
                    float py = c[mi][4][nt][ai];
                    float ig = sigm(ci + px + __ldg(cb + oc));
                    float og = sigm(co + py + __ldg(cb + 128 + oc));
                    float gg = ftanh(cg + py + __ldg(cb + 192 + oc));
                    orow[oc] = og * ftanh(ig * gg);
                }
            }
        }
    }
}

// ---------------------------------------------------------------------------
extern "C" void kernel_launch(void* const* d_in, const int* in_sizes, int n_in,
                              void* d_out, int out_size) {
    const float* x      = (const float*)d_in[0];
    const float* cw0    = (const float*)d_in[1];
    const float* cb0    = (const float*)d_in[2];
    const float* pxw0   = (const float*)d_in[3];
    const float* pyw0   = (const float*)d_in[4];
    const float* qkvw0  = (const float*)d_in[5];
    const float* projw0 = (const float*)d_in[6];
    const float* projb0 = (const float*)d_in[7];
    const float* cw1    = (const float*)d_in[8];
    const float* cb1    = (const float*)d_in[9];
    const float* pxw1   = (const float*)d_in[10];
    const float* pyw1   = (const float*)d_in[11];
    const float* qkvw1  = (const float*)d_in[12];
    const float* projw1 = (const float*)d_in[13];
    const float* projb1 = (const float*)d_in[14];
    const float* outw   = (const float*)d_in[15];
    const float* outb   = (const float*)d_in[16];
    float* out = (float*)d_out;

    cudaFuncSetAttribute(win_attn_tc, cudaFuncAttributeMaxDynamicSharedMemorySize,
                         AT_SMEM);
    cudaFuncSetAttribute(layer1_tc, cudaFuncAttributeMaxDynamicSharedMemorySize,
                         L1_SMEM_TOTAL);

    // layer0 (blocks 0..1023) + prep piggyback (blocks 1024..)
    layer0_gates<<<1024 + PREP_BLOCKS, 256>>>(x, cw0, cb0, pxw0, pyw0,
                                              cw1, pxw1, pyw1,
                                              qkvw0, projw0, qkvw1, projw1);
    win_attn_tc<<<4096, 256, AT_SMEM>>>(0, projb0, outw, outb, out, 1); // buf0 -> h16
    layer1_tc<<<2048, 512, L1_SMEM_TOTAL>>>(cb1);                       // h16 -> buf0
    win_attn_tc<<<4096, 256, AT_SMEM>>>(1, projb1, outw, outb, out, 0); // buf0 -> out
}

// round 15
// speedup vs baseline: 1.2717x; 1.0738x over previous
#include <cuda_runtime.h>
#include <cuda_fp16.h>
#include <math.h>
#include <stdint.h>

#define BATCH 16
#define HDIM 128
#define WDIM 128
#define HID 64

typedef uint32_t u32;
typedef uint16_t u16;

// layer-0 output h (NHWC fp32); consumed by attention pass 0; reused for h1
__device__ __align__(16) float g_buf0[BATCH * HDIM * WDIM * HID];
// padded f16 activations for layer-1 conv: [16][130][130][64]
__device__ __align__(16) __half g_h16[BATCH * 130 * 130 * HID];
// f16 layer-1 weights: [tap 9][gate*64+oc 320][cin 64]
__device__ __align__(16) __half g_w1h[9 * 320 * 64];
// f16 attention weights: qkv hi only [192][64]; proj hi/lo [64][64]
__device__ __align__(16) __half g_wqh[2][192 * 64];
__device__ __align__(16) __half g_wph[2][64 * 64];
__device__ __align__(16) __half g_wpl[2][64 * 64];

__device__ __forceinline__ float sigm(float v) {
    return __fdividef(1.0f, 1.0f + __expf(-v));
}
__device__ __forceinline__ float ftanh(float v) {
    return 1.0f - __fdividef(2.0f, __expf(2.0f * v) + 1.0f);
}

// ===================== sm_80+ tensor helpers (no 'a' target) ================
__device__ __forceinline__ u32 smem_u32(const void* p) {
    u32 a;
    asm("{ .reg .u64 t; cvta.to.shared.u64 t, %1; cvt.u32.u64 %0, t; }"
        : "=r"(a) : "l"(p));
    return a;
}
__device__ __forceinline__ void cp16(u32 dst, const void* src) {
    asm volatile("cp.async.cg.shared.global [%0], [%1], 16;" :: "r"(dst), "l"(src));
}
#define CPASYNC_COMMIT() asm volatile("cp.async.commit_group;" ::: "memory")
#define CPASYNC_WAIT0()  asm volatile("cp.async.wait_group 0;" ::: "memory")

__device__ __forceinline__ void ldsm4(u32* r, u32 a) {
    asm volatile("ldmatrix.sync.aligned.m8n8.x4.shared.b16 {%0,%1,%2,%3}, [%4];"
                 : "=r"(r[0]), "=r"(r[1]), "=r"(r[2]), "=r"(r[3]) : "r"(a));
}
__device__ __forceinline__ void mma16816(float* c, const u32* a, u32 b0, u32 b1) {
    asm volatile(
        "mma.sync.aligned.m16n8k16.row.col.f32.f16.f16.f32 "
        "{%0,%1,%2,%3}, {%4,%5,%6,%7}, {%8,%9}, {%0,%1,%2,%3};"
        : "+f"(c[0]), "+f"(c[1]), "+f"(c[2]), "+f"(c[3])
        : "r"(a[0]), "r"(a[1]), "r"(a[2]), "r"(a[3]), "r"(b0), "r"(b1));
}
__device__ __forceinline__ u32 pk2(float lo, float hi) {   // {lo | hi<<16}
    u32 r;
    asm("cvt.rn.f16x2.f32 %0, %1, %2;" : "=r"(r) : "f"(hi), "f"(lo));
    return r;
}
// f16 hi/lo split of a float pair
__device__ __forceinline__ void split2(float a, float b, u32& hi, u32& lo) {
    __half ha = __float2half_rn(a), hb = __float2half_rn(b);
    hi = ((u32)__half_as_ushort(hb) << 16) | (u32)__half_as_ushort(ha);
    lo = pk2(a - __half2float(ha), b - __half2float(hb));
}
__device__ __forceinline__ void sts32(u32 addr, u32 v) {
    asm volatile("st.shared.b32 [%0], %1;" :: "r"(addr), "r"(v));
}
__device__ __forceinline__ void sts16(u32 addr, float v) {
    u16 b = __half_as_ushort(__float2half_rn(v));
    asm volatile("st.shared.b16 [%0], %1;" :: "r"(addr), "h"(b) : "memory");
}

// ---------------------------------------------------------------------------
// Prep work sizes (executed by extra blocks of the layer0 launch)
// ---------------------------------------------------------------------------
#define PREP_A (9 * 320 * 64)          // 184320
#define PREP_B (BATCH * 130 * 130)     // 270400
#define PREP_C (192 * 64)              // 12288
#define PREP_D (64 * 64)               // 4096
#define PREP_TOTAL (PREP_A + PREP_B + PREP_C + PREP_D)
#define PREP_BLOCKS ((PREP_TOTAL + 255) / 256)

__device__ __forceinline__ void do_prep(
    int idx,
    const float* __restrict__ cw, const float* __restrict__ pxw,
    const float* __restrict__ pyw,
    const float* __restrict__ q0, const float* __restrict__ p0,
    const float* __restrict__ q1, const float* __restrict__ p1) {
    if (idx < PREP_A) {
        int tap = idx / (320 * 64);
        int rem = idx % (320 * 64);
        int r = rem / 64, cin = rem % 64;
        int g = r >> 6, n = r & 63;
        float v;
        if (g == 0)      v = cw[(n * 128 + cin) * 9 + tap];
        else if (g == 1) v = cw[((128 + n) * 128 + cin) * 9 + tap];
        else if (g == 2) v = cw[((192 + n) * 128 + cin) * 9 + tap];
        else if (g == 3) v = pxw[(n * 64 + cin) * 9 + tap];
        else             v = pyw[(n * 64 + cin) * 9 + tap];
        g_w1h[idx] = __float2half_rn(v);
        return;
    }
    idx -= PREP_A;
    if (idx < PREP_B) {
        int bp = idx % (130 * 130);
        int yy = bp / 130, xx = bp % 130;
        if (yy == 0 || yy == 129 || xx == 0 || xx == 129) {
            uint4* d = (uint4*)(g_h16 + (size_t)idx * 64);
            uint4 z = {0, 0, 0, 0};
#pragma unroll
            for (int i = 0; i < 8; i++) d[i] = z;
        }
        return;
    }
    idx -= PREP_B;
    if (idx < PREP_C) {
        g_wqh[0][idx] = __float2half_rn(q0[idx]);
        g_wqh[1][idx] = __float2half_rn(q1[idx]);
        return;
    }
    idx -= PREP_C;
    if (idx < PREP_D) {
        float v0 = p0[idx], v1 = p1[idx];
        __half h0 = __float2half_rn(v0), h1 = __float2half_rn(v1);
        g_wph[0][idx] = h0; g_wpl[0][idx] = __float2half_rn(v0 - __half2float(h0));
        g_wph[1][idx] = h1; g_wpl[1][idx] = __float2half_rn(v1 - __half2float(h1));
    }
}

// ---------------------------------------------------------------------------
// Layer 0 fused gates + prep piggyback blocks.
// ---------------------------------------------------------------------------
__global__ __launch_bounds__(256) void layer0_gates(
    const float* __restrict__ x, const float* __restrict__ cw,
    const float* __restrict__ cb, const float* __restrict__ pxw,
    const float* __restrict__ pyw,
    const float* __restrict__ cw1, const float* __restrict__ pxw1,
    const float* __restrict__ pyw1,
    const float* __restrict__ q0, const float* __restrict__ p0,
    const float* __restrict__ q1, const float* __restrict__ p1) {
    __shared__ float s_w[64 * 48];
    __shared__ float s_b[3][64];
    __shared__ float s_out[256 * 20];
    int tid = threadIdx.x;

    if (blockIdx.x >= 1024) {
        int idx = (blockIdx.x - 1024) * 256 + tid;
        do_prep(idx, cw1, pxw1, pyw1, q0, p0, q1, p1);
        return;
    }

    for (int i = tid; i < 64 * 45; i += 256) {
        int c = i / 45, j = i % 45;
        int g = j / 9, tap = j % 9;
        float v;
        if (g == 0)      v = cw[c * 585 + tap];
        else if (g == 1) v = cw[(128 + c) * 585 + tap];
        else if (g == 2) v = cw[(192 + c) * 585 + tap];
        else if (g == 3) v = pxw[c * 9 + tap];
        else             v = pyw[c * 9 + tap];
        s_w[c * 48 + j] = v;
    }
    if (tid < 64) {
        s_b[0][tid] = cb[tid];
        s_b[1][tid] = cb[128 + tid];
        s_b[2][tid] = cb[192 + tid];
    }
    __syncthreads();

    int p = blockIdx.x * 256 + tid;
    int b = p >> 14, y = (p >> 7) & 127, xc = p & 127;
    float pv[9];
#pragma unroll
    for (int ky = 0; ky < 3; ky++)
#pragma unroll
        for (int kx = 0; kx < 3; kx++) {
            int gy = y + ky - 1, gx = xc + kx - 1;
            pv[ky * 3 + kx] = (gy >= 0 && gy < 128 && gx >= 0 && gx < 128)
                                  ? x[(b << 14) + gy * 128 + gx] : 0.0f;
        }

#pragma unroll 1
    for (int chunk = 0; chunk < 4; chunk++) {
        float4 ov;
#pragma unroll
        for (int cc = 0; cc < 16; cc++) {
            int c = chunk * 16 + cc;
            float wv[48];
            const float4* w4 = (const float4*)(s_w + c * 48);
#pragma unroll
            for (int q = 0; q < 12; q++) {
                float4 t4 = w4[q];
                wv[q * 4 + 0] = t4.x; wv[q * 4 + 1] = t4.y;
                wv[q * 4 + 2] = t4.z; wv[q * 4 + 3] = t4.w;
            }
            float aci = 0.f, aco = 0.f, acg = 0.f, apx = 0.f, apy = 0.f;
#pragma unroll
            for (int tap = 0; tap < 9; tap++) {
                float a = pv[tap];
                aci += a * wv[tap];
                aco += a * wv[9 + tap];
                acg += a * wv[18 + tap];
                apx += a * wv[27 + tap];
                apy += a * wv[36 + tap];
            }
            float ig = sigm(aci + apx + s_b[0][c]);
            float og = sigm(aco + apy + s_b[1][c]);
            float gg = ftanh(acg + apy + s_b[2][c]);
            float r = og * ftanh(ig * gg);
            int e = cc & 3;
            if (e == 0) ov.x = r; else if (e == 1) ov.y = r;
            else if (e == 2) ov.z = r;
            else {
                ov.w = r;
                *(float4*)(s_out + tid * 20 + (cc >> 2) * 4) = ov;
            }
        }
        __syncthreads();
#pragma unroll
        for (int it = 0; it < 4; it++) {
            int i = it * 256 + tid;
            int pp = i >> 2, k = i & 3;
            float4 v4 = *(const float4*)(s_out + pp * 20 + k * 4);
            *(float4*)(g_buf0 +
                       ((size_t)(blockIdx.x * 256 + pp)) * 64 + chunk * 16 + k * 4) = v4;
        }
        __syncthreads();
    }
}

// ---------------------------------------------------------------------------
// Window attention on mma.sync, 8 warps/window. Hi/lo compensation on all
// ACTIVATIONS (x,Q,K,V,P,O) and proj weights; QKV weights hi-only (the two
// dropped sources cost ~2.7e-4 each in quadrature, saving 1/3 of phase-1 MMA).
// ---------------------------------------------------------------------------
#define AT_XH 0
#define AT_XL 8192
#define AT_QH 16384
#define AT_QL 24576
#define AT_KH 32768
#define AT_KL 40960
#define AT_VTH 49152
#define AT_VTL 57344
#define AT_WQH 65536
#define AT_RED 90112
#define AT_SMEM 90624

__global__ __launch_bounds__(256, 2) void win_attn_tc(
    int layer, const float* __restrict__ projb,
    const float* __restrict__ outw, const float* __restrict__ outb,
    float* __restrict__ out, int to_h16) {
    extern __shared__ char smem[];
    u32 sb = smem_u32(smem);
    int tid = threadIdx.x, lane = tid & 31, w = tid >> 5;
    int wid = blockIdx.x;
    int b = wid >> 8, wy = (wid >> 4) & 15, wx = wid & 15;
    int base = ((b * 128 + wy * 8) * 128 + wx * 8) * 64;

    // ---- stage qkv weights (hi only) ----
    if (tid < 192) {
        int r = tid;
        const __half* sh = g_wqh[layer] + r * 64;
        u32 row = (u32)r * 128, sw = (u32)((r & 7) << 4);
#pragma unroll
        for (int i = 0; i < 8; i++)
            cp16(sb + AT_WQH + ((row + i * 16) ^ sw), (const char*)sh + i * 16);
    }
    CPASYNC_COMMIT();
    {
        int row = tid >> 2, q = tid & 3;              // token row, 16-col quarter
        int ty = row >> 3, tx = row & 7;
        const float* src = g_buf0 + base + (ty * 128 + tx) * 64 + q * 16;
        u32 sw = (u32)((row & 7) << 4);
#pragma unroll
        for (int j = 0; j < 4; j++) {
            float4 a = *(const float4*)(src + j * 4);
            u32 byte0 = (u32)(row * 128 + q * 32 + j * 8);
            u32 h01, l01, h23, l23;
            split2(a.x, a.y, h01, l01);
            split2(a.z, a.w, h23, l23);
            sts32(sb + AT_XH + (byte0 ^ sw), h01);
            sts32(sb + AT_XL + (byte0 ^ sw), l01);
            sts32(sb + AT_XH + ((byte0 + 4) ^ sw), h23);
            sts32(sb + AT_XL + ((byte0 + 4) ^ sw), l23);
        }
    }
    CPASYNC_WAIT0();
    __syncthreads();

    // lane-invariant ldsm address pieces
    int aRow = (lane & 7) + 8 * ((lane >> 3) & 1);
    u32 aKl = (u32)(16 * (lane >> 4));
    int bRow = ((lane >> 4) & 1) * 8 + (lane & 7);
    u32 bKl = (u32)(((lane >> 3) & 1) * 16);
    int g = lane >> 2, t = lane & 3;

    // ---- phase 1: QKV GEMM (2-term: Ah*Bh + Al*Bh). warp = (ocg, mh) ----
    {
        int ocg = w >> 1, mh = w & 1;
        float c[2][6][4];
#pragma unroll
        for (int mtl = 0; mtl < 2; mtl++)
#pragma unroll
            for (int nt = 0; nt < 6; nt++)
#pragma unroll
                for (int e = 0; e < 4; e++) c[mtl][nt][e] = 0.0f;

#pragma unroll
        for (int ks = 0; ks < 4; ks++) {
            u32 ah[2][4], al[2][4];
#pragma unroll
            for (int mtl = 0; mtl < 2; mtl++) {
                u32 ar = (u32)((mh * 2 + mtl) * 16 + aRow);
                u32 off = ar * 128 + (u32)(ks * 32) + aKl;
                u32 sw = ((ar & 7) << 4);
                ldsm4(ah[mtl], sb + AT_XH + (off ^ sw));
                ldsm4(al[mtl], sb + AT_XL + (off ^ sw));
            }
#pragma unroll
            for (int np = 0; np < 3; np++) {
                u32 bh[4];
                u32 nr = (u32)(ocg * 48 + np * 16 + bRow);
                u32 off = nr * 128 + (u32)(ks * 32) + bKl;
                u32 sw = ((nr & 7) << 4);
                ldsm4(bh, sb + AT_WQH + (off ^ sw));
#pragma unroll
                for (int mtl = 0; mtl < 2; mtl++) {
                    mma16816(c[mtl][np * 2], ah[mtl], bh[0], bh[1]);
                    mma16816(c[mtl][np * 2], al[mtl], bh[0], bh[1]);
                    mma16816(c[mtl][np * 2 + 1], ah[mtl], bh[2], bh[3]);
                    mma16816(c[mtl][np * 2 + 1], al[mtl], bh[2], bh[3]);
                }
            }
        }
        // store Q (x0.25), K, V^T as f16 hi/lo
#pragma unroll
        for (int mtl = 0; mtl < 2; mtl++) {
            int mt = (w & 1) * 2 + mtl;
#pragma unroll
            for (int nt = 0; nt < 6; nt++) {
                int nc = ocg * 48 + nt * 8 + t * 2;
                int r0 = mt * 16 + g, r1 = r0 + 8;
                float v0 = c[mtl][nt][0], v1 = c[mtl][nt][1];
                float v2 = c[mtl][nt][2], v3 = c[mtl][nt][3];
                u32 sw0 = ((u32)(r0 & 7) << 4), sw1 = ((u32)(r1 & 7) << 4);
                if (nc < 64) {
                    u32 h01, l01, h23, l23;
                    split2(v0 * 0.25f, v1 * 0.25f, h01, l01);
                    split2(v2 * 0.25f, v3 * 0.25f, h23, l23);
                    u32 o0 = ((u32)(r0 * 128 + nc * 2)) ^ sw0;
                    u32 o1 = ((u32)(r1 * 128 + nc * 2)) ^ sw1;
                    sts32(sb + AT_QH + o0, h01); sts32(sb + AT_QL + o0, l01);
                    sts32(sb + AT_QH + o1, h23); sts32(sb + AT_QL + o1, l23);
                } else if (nc < 128) {
                    int kc = nc - 64;
                    u32 h01, l01, h23, l23;
                    split2(v0, v1, h01, l01);
                    split2(v2, v3, h23, l23);
                    u32 o0 = ((u32)(r0 * 128 + kc * 2)) ^ sw0;
                    u32 o1 = ((u32)(r1 * 128 + kc * 2)) ^ sw1;
                    sts32(sb + AT_KH + o0, h01); sts32(sb + AT_KL + o0, l01);
                    sts32(sb + AT_KH + o1, h23); sts32(sb + AT_KL + o1, l23);
                } else {
                    int d0 = nc - 128, d1 = d0 + 1;
                    u32 s0 = (u32)((d0 & 7) << 4), s1 = (u32)((d1 & 7) << 4);
                    float vv[4] = {v0, v1, v2, v3};
                    int dd[4] = {d0, d1, d0, d1};
                    int rr[4] = {r0, r0, r1, r1};
                    u32 ss[4] = {s0, s1, s0, s1};
#pragma unroll
                    for (int e = 0; e < 4; e++) {
                        __half h = __float2half_rn(vv[e]);
                        float rl = vv[e] - __half2float(h);
                        u32 off = ((u32)(dd[e] * 128 + rr[e] * 2)) ^ ss[e];
                        sts16(sb + AT_VTH + off, vv[e]);
                        sts16(sb + AT_VTL + off, rl);
                    }
                }
            }
        }
    }
    __syncthreads();

    // ---- phase 2: attention, warp = (head, mt-half) ----
    {
        int h = w >> 1, mh = w & 1;
        u32 kbh[4][4], kbl[4][4], vbh[4][4], vbl[4][4];
#pragma unroll
        for (int np = 0; np < 4; np++) {
            u32 nr = (u32)(np * 16 + bRow);
            u32 off = nr * 128 + (u32)(h * 32) + bKl;
            u32 sw = ((nr & 7) << 4);
            ldsm4(kbh[np], sb + AT_KH + (off ^ sw));
            ldsm4(kbl[np], sb + AT_KL + (off ^ sw));
        }
#pragma unroll
        for (int ks = 0; ks < 4; ks++) {
            u32 nr = (u32)(h * 16 + bRow);
            u32 off = nr * 128 + (u32)(ks * 32) + bKl;
            u32 sw = ((nr & 7) << 4);
            ldsm4(vbh[ks], sb + AT_VTH + (off ^ sw));
            ldsm4(vbl[ks], sb + AT_VTL + (off ^ sw));
        }
        __syncthreads();   // all warps hold K/V fragments; vt planes now free
        // stage proj weights hi/lo into the vt planes (overlap with compute)
        if (tid < 128) {
            int r = tid & 63;
            const __half* src = (tid < 64) ? (g_wph[layer] + r * 64)
                                           : (g_wpl[layer] + r * 64);
            u32 dstb = (tid < 64) ? (sb + AT_VTH) : (sb + AT_VTL);
            u32 row = (u32)r * 128, sw = (u32)((r & 7) << 4);
#pragma unroll
            for (int i = 0; i < 8; i++)
                cp16(dstb + ((row + i * 16) ^ sw), (const char*)src + i * 16);
        }
        CPASYNC_COMMIT();

#pragma unroll
        for (int mtl = 0; mtl < 2; mtl++) {
            int mt = mh * 2 + mtl;
            u32 aqh[4], aql[4];
            u32 ar = (u32)(mt * 16 + aRow);
            u32 off = ar * 128 + (u32)(h * 32) + aKl;
            u32 sw = ((ar & 7) << 4);
            ldsm4(aqh, sb + AT_QH + (off ^ sw));
            ldsm4(aql, sb + AT_QL + (off ^ sw));

            float s[8][4];
#pragma unroll
            for (int nt = 0; nt < 8; nt++)
#pragma unroll
                for (int e = 0; e < 4; e++) s[nt][e] = 0.0f;
#pragma unroll
            for (int np = 0; np < 4; np++) {
                mma16816(s[np * 2], aqh, kbh[np][0], kbh[np][1]);
                mma16816(s[np * 2], aql, kbh[np][0], kbh[np][1]);
                mma16816(s[np * 2], aqh, kbl[np][0], kbl[np][1]);
                mma16816(s[np * 2 + 1], aqh, kbh[np][2], kbh[np][3]);
                mma16816(s[np * 2 + 1], aql, kbh[np][2], kbh[np][3]);
                mma16816(s[np * 2 + 1], aqh, kbl[np][2], kbl[np][3]);
            }
            // softmax rows (mt*16+g) and (+8)
            float m0 = -1e30f, m1 = -1e30f;
#pragma unroll
            for (int nt = 0; nt < 8; nt++) {
                m0 = fmaxf(m0, fmaxf(s[nt][0], s[nt][1]));
                m1 = fmaxf(m1, fmaxf(s[nt][2], s[nt][3]));
            }
            m0 = fmaxf(m0, __shfl_xor_sync(0xffffffff, m0, 1));
            m0 = fmaxf(m0, __shfl_xor_sync(0xffffffff, m0, 2));
            m1 = fmaxf(m1, __shfl_xor_sync(0xffffffff, m1, 1));
            m1 = fmaxf(m1, __shfl_xor_sync(0xffffffff, m1, 2));
            float s0 = 0.f, s1 = 0.f;
#pragma unroll
            for (int nt = 0; nt < 8; nt++) {
                s[nt][0] = __expf(s[nt][0] - m0); s0 += s[nt][0];
                s[nt][1] = __expf(s[nt][1] - m0); s0 += s[nt][1];
                s[nt][2] = __expf(s[nt][2] - m1); s1 += s[nt][2];
                s[nt][3] = __expf(s[nt][3] - m1); s1 += s[nt][3];
            }
            s0 += __shfl_xor_sync(0xffffffff, s0, 1);
            s0 += __shfl_xor_sync(0xffffffff, s0, 2);
            s1 += __shfl_xor_sync(0xffffffff, s1, 1);
            s1 += __shfl_xor_sync(0xffffffff, s1, 2);
            float i0 = 1.0f / s0, i1 = 1.0f / s1;

            float o[2][4];
#pragma unroll
            for (int nt = 0; nt < 2; nt++)
#pragma unroll
                for (int e = 0; e < 4; e++) o[nt][e] = 0.0f;
#pragma unroll
            for (int ks = 0; ks < 4; ks++) {
                u32 ph[4], pl[4];
                split2(s[2 * ks][0], s[2 * ks][1], ph[0], pl[0]);
                split2(s[2 * ks][2], s[2 * ks][3], ph[1], pl[1]);
                split2(s[2 * ks + 1][0], s[2 * ks + 1][1], ph[2], pl[2]);
                split2(s[2 * ks + 1][2], s[2 * ks + 1][3], ph[3], pl[3]);
                mma16816(o[0], ph, vbh[ks][0], vbh[ks][1]);
                mma16816(o[0], pl, vbh[ks][0], vbh[ks][1]);
                mma16816(o[0], ph, vbl[ks][0], vbl[ks][1]);
                mma16816(o[1], ph, vbh[ks][2], vbh[ks][3]);
                mma16816(o[1], pl, vbh[ks][2], vbh[ks][3]);
                mma16816(o[1], ph, vbl[ks][2], vbl[ks][3]);
            }
            // scale + store O hi/lo to x planes
            int r0 = mt * 16 + g, r1 = r0 + 8;
            u32 sw0 = ((u32)(r0 & 7) << 4), sw1 = ((u32)(r1 & 7) << 4);
#pragma unroll
            for (int nt = 0; nt < 2; nt++) {
                int dc = h * 16 + nt * 8 + t * 2;
                u32 h01, l01, h23, l23;
                split2(o[nt][0] * i0, o[nt][1] * i0, h01, l01);
                split2(o[nt][2] * i1, o[nt][3] * i1, h23, l23);
                u32 o0 = ((u32)(r0 * 128 + dc * 2)) ^ sw0;
                u32 o1 = ((u32)(r1 * 128 + dc * 2)) ^ sw1;
                sts32(sb + AT_XH + o0, h01); sts32(sb + AT_XL + o0, l01);
                sts32(sb + AT_XH + o1, h23); sts32(sb + AT_XL + o1, l23);
            }
        }
    }
    CPASYNC_WAIT0();
    __syncthreads();

    // ---- phase 3: proj GEMM (3-term), warp = (m-tile, n-half) ----
    {
        int mtile = w >> 1, nh = w & 1;
        float c[4][4];
#pragma unroll
        for (int nt = 0; nt < 4; nt++)
#pragma unroll
            for (int e = 0; e < 4; e++) c[nt][e] = 0.0f;
#pragma unroll
        for (int ks = 0; ks < 4; ks++) {
            u32 ah[4], al[4];
            u32 ar = (u32)(mtile * 16 + aRow);
            u32 off = ar * 128 + (u32)(ks * 32) + aKl;
            u32 sw = ((ar & 7) << 4);
            ldsm4(ah, sb + AT_XH + (off ^ sw));
            ldsm4(al, sb + AT_XL + (off ^ sw));
#pragma unroll
            for (int npl = 0; npl < 2; npl++) {
                int np = nh * 2 + npl;
                u32 bh[4], bl[4];
                u32 nr = (u32)(np * 16 + bRow);
                u32 boff = nr * 128 + (u32)(ks * 32) + bKl;
                u32 bsw = ((nr & 7) << 4);
                ldsm4(bh, sb + AT_VTH + (boff ^ bsw));
                ldsm4(bl, sb + AT_VTL + (boff ^ bsw));
                mma16816(c[npl * 2], ah, bh[0], bh[1]);
                mma16816(c[npl * 2], al, bh[0], bh[1]);
                mma16816(c[npl * 2], ah, bl[0], bl[1]);
                mma16816(c[npl * 2 + 1], ah, bh[2], bh[3]);
                mma16816(c[npl * 2 + 1], al, bh[2], bh[3]);
                mma16816(c[npl * 2 + 1], ah, bl[2], bl[3]);
            }
        }
        if (to_h16) {
#pragma unroll
            for (int ntl = 0; ntl < 4; ntl++) {
                int nt = nh * 4 + ntl;
                int cc = nt * 8 + t * 2;
                float b0 = __ldg(projb + cc), b1 = __ldg(projb + cc + 1);
#pragma unroll
                for (int rh = 0; rh < 2; rh++) {
                    int tok = mtile * 16 + g + rh * 8;
                    int ty = tok >> 3, tx = tok & 7;
                    float v0 = c[ntl][rh * 2] + b0, v1 = c[ntl][rh * 2 + 1] + b1;
                    int gy = wy * 8 + ty, gx = wx * 8 + tx;
                    __half* dst = g_h16 +
                        ((size_t)((b * 130 + gy + 1) * 130 + gx + 1)) * 64 + cc;
                    *(__half2*)dst = __floats2half2_rn(v0, v1);
                }
            }
        } else {
            float* s_red = (float*)(smem + AT_RED);    // [4 mtile][2 nh][8 g][2 rh]
            float acc0 = 0.0f, acc1 = 0.0f;
#pragma unroll
            for (int ntl = 0; ntl < 4; ntl++) {
                int cc = (nh * 4 + ntl) * 8 + t * 2;
                float b0 = __ldg(projb + cc), b1 = __ldg(projb + cc + 1);
                float w0 = __ldg(outw + cc), w1 = __ldg(outw + cc + 1);
                acc0 += (c[ntl][0] + b0) * w0 + (c[ntl][1] + b1) * w1;
                acc1 += (c[ntl][2] + b0) * w0 + (c[ntl][3] + b1) * w1;
            }
            acc0 += __shfl_xor_sync(0xffffffff, acc0, 1);
            acc0 += __shfl_xor_sync(0xffffffff, acc0, 2);
            acc1 += __shfl_xor_sync(0xffffffff, acc1, 1);
            acc1 += __shfl_xor_sync(0xffffffff, acc1, 2);
            if (t == 0) {
                s_red[((mtile * 2 + nh) * 8 + g) * 2 + 0] = acc0;
                s_red[((mtile * 2 + nh) * 8 + g) * 2 + 1] = acc1;
            }
            __syncthreads();
            if (tid < 64) {
                int mt2 = tid >> 4, g2 = (tid >> 1) & 7, rh2 = tid & 1;
                float v = s_red[((mt2 * 2 + 0) * 8 + g2) * 2 + rh2] +
                          s_red[((mt2 * 2 + 1) * 8 + g2) * 2 + rh2] + __ldg(outb);
                int tok = mt2 * 16 + g2 + rh2 * 8;
                int ty = tok >> 3, tx = tok & 7;
                int gy = wy * 8 + ty, gx = wx * 8 + tx;
                out[(b * 128 + gy) * 128 + gx] = v;
            }
        }
    }
}

// ---------------------------------------------------------------------------
// Layer 1 conv on mma.sync (round-10 version: full row, 512 thr, 2-stage B)
// ---------------------------------------------------------------------------
#define L1_A_OFF 0
#define L1_A_BYTES (390 * 128)
#define L1_B0 L1_A_BYTES
#define L1_B_BYTES (320 * 128)
#define L1_B1 (L1_B0 + L1_B_BYTES)
#define L1_SMEM_TOTAL (L1_B1 + L1_B_BYTES)   // 131840

__device__ __forceinline__ void l1_load_B(u32 sB, int tap, int tid) {
    if (tid < 320) {
        const __half* src = g_w1h + (size_t)(tap * 320 + tid) * 64;
        u32 row = tid * 128;
        u32 sw = (u32)((tid & 7) << 4);
#pragma unroll
        for (int i = 0; i < 8; i++)
            cp16(sB + ((row + i * 16) ^ sw), (const char*)src + i * 16);
    }
}

__global__ __launch_bounds__(512, 1) void layer1_tc(const float* __restrict__ cb) {
    extern __shared__ char smem[];
    u32 sb = smem_u32(smem);
    int tid = threadIdx.x, lane = tid & 31, warp = tid >> 5;
    int wm = warp & 3, wn = warp >> 2;
    int tile = blockIdx.x;
    int b = tile >> 7, y = tile & 127;

    if (tid < 390) {
        int rowIdx = tid / 130, col = tid % 130;
        const __half* src = g_h16 +
            ((size_t)((b * 130 + y + rowIdx) * 130 + col)) * 64;
        u32 row = (u32)tid * 128;
        u32 sw = (u32)((tid & 7) << 4);
#pragma unroll
        for (int i = 0; i < 8; i++)
            cp16(sb + L1_A_OFF + ((row + i * 16) ^ sw), (const char*)src + i * 16);
    }
    l1_load_B(sb + L1_B0, 0, tid);
    CPASYNC_COMMIT();
    CPASYNC_WAIT0();
    __syncthreads();

    float c[2][5][2][4];
#pragma unroll
    for (int mi = 0; mi < 2; mi++)
#pragma unroll
        for (int g5 = 0; g5 < 5; g5++)
#pragma unroll
            for (int nt = 0; nt < 2; nt++)
#pragma unroll
                for (int e = 0; e < 4; e++) c[mi][g5][nt][e] = 0.0f;

    int arow = wm * 32 + (lane & 7) + 8 * ((lane >> 3) & 1);
    u32 aklane = (u32)(16 * (lane >> 4));
    u32 bkl = (u32)(((lane >> 3) & 1) * 16);
    int bnrow_base = wn * 16 + ((lane >> 4) & 1) * 8 + (lane & 7);
    u32 bswz = (u32)((lane & 7) << 4);

#pragma unroll 1
    for (int tap = 0; tap < 9; tap++) {
        u32 Bb = sb + ((tap & 1) ? L1_B1 : L1_B0);
        if (tap < 8) {
            l1_load_B(sb + ((tap & 1) ? L1_B0 : L1_B1), tap + 1, tid);
            CPASYNC_COMMIT();
        }
        int dy = tap / 3, dx = tap % 3;
        int br0 = dy * 130 + arow + dx;
#pragma unroll
        for (int ks = 0; ks < 4; ks++) {
            u32 a[2][4];
#pragma unroll
            for (int mi = 0; mi < 2; mi++) {
                u32 br = (u32)(br0 + mi * 16);
                u32 off = br * 128 + (u32)(ks * 32) + aklane;
                ldsm4(a[mi], sb + L1_A_OFF + (off ^ ((br & 7) << 4)));
            }
#pragma unroll
            for (int g5 = 0; g5 < 5; g5++) {
                u32 bfr[4];
                u32 nrow = (u32)(g5 * 64 + bnrow_base);
                u32 off = nrow * 128 + (u32)(ks * 32) + bkl;
                ldsm4(bfr, Bb + (off ^ bswz));
#pragma unroll
                for (int mi = 0; mi < 2; mi++) {
                    mma16816(c[mi][g5][0], a[mi], bfr[0], bfr[1]);
                    mma16816(c[mi][g5][1], a[mi], bfr[2], bfr[3]);
                }
            }
        }
        if (tap < 8) { CPASYNC_WAIT0(); }
        __syncthreads();
    }

    int q = lane & 3, gr = lane >> 2;
    int ocB = wn * 16;
#pragma unroll
    for (int mi = 0; mi < 2; mi++) {
#pragma unroll
        for (int rh = 0; rh < 2; rh++) {
            int x = wm * 32 + mi * 16 + gr + rh * 8;
            float* orow = g_buf0 + ((size_t)((b * 128 + y) * 128 + x)) * 64;
#pragma unroll
            for (int nt = 0; nt < 2; nt++) {
#pragma unroll
                for (int e = 0; e < 2; e++) {
                    int oc = ocB + nt * 8 + q * 2 + e;
                    int ai = rh * 2 + e;
                    float ci = c[mi][0][nt][ai];
                    float co = c[mi][1][nt][ai];
                    float cg = c[mi][2][nt][ai];
                    float px = c[mi][3][nt][ai];
                    float py = c[mi][4][nt][ai];
                    float ig = sigm(ci + px + __ldg(cb + oc));
                    float og = sigm(co + py + __ldg(cb + 128 + oc));
                    float gg = ftanh(cg + py + __ldg(cb + 192 + oc));
                    orow[oc] = og * ftanh(ig * gg);
                }
            }
        }
    }
}

// ---------------------------------------------------------------------------
extern "C" void kernel_launch(void* const* d_in, const int* in_sizes, int n_in,
                              void* d_out, int out_size) {
    const float* x      = (const float*)d_in[0];
    const float* cw0    = (const float*)d_in[1];
    const float* cb0    = (const float*)d_in[2];
    const float* pxw0   = (const float*)d_in[3];
    const float* pyw0   = (const float*)d_in[4];
    const float* qkvw0  = (const float*)d_in[5];
    const float* projw0 = (const float*)d_in[6];
    const float* projb0 = (const float*)d_in[7];
    const float* cw1    = (const float*)d_in[8];
    const float* cb1    = (const float*)d_in[9];
    const float* pxw1   = (const float*)d_in[10];
    const float* pyw1   = (const float*)d_in[11];
    const float* qkvw1  = (const float*)d_in[12];
    const float* projw1 = (const float*)d_in[13];
    const float* projb1 = (const float*)d_in[14];
    const float* outw   = (const float*)d_in[15];
    const float* outb   = (const float*)d_in[16];
    float* out = (float*)d_out;

    cudaFuncSetAttribute(win_attn_tc, cudaFuncAttributeMaxDynamicSharedMemorySize,
                         AT_SMEM);
    cudaFuncSetAttribute(layer1_tc, cudaFuncAttributeMaxDynamicSharedMemorySize,
                         L1_SMEM_TOTAL);

    // layer0 (blocks 0..1023) + prep piggyback (blocks 1024..)
    layer0_gates<<<1024 + PREP_BLOCKS, 256>>>(x, cw0, cb0, pxw0, pyw0,
                                              cw1, pxw1, pyw1,
                                              qkvw0, projw0, qkvw1, projw1);
    win_attn_tc<<<4096, 256, AT_SMEM>>>(0, projb0, outw, outb, out, 1); // buf0 -> h16
    layer1_tc<<<2048, 512, L1_SMEM_TOTAL>>>(cb1);                       // h16 -> buf0
    win_attn_tc<<<4096, 256, AT_SMEM>>>(1, projb1, outw, outb, out, 0); // buf0 -> out
}

// round 16
// speedup vs baseline: 1.2995x; 1.0219x over previous
#include <cuda_runtime.h>
#include <cuda_fp16.h>
#include <math.h>
#include <stdint.h>

#define BATCH 16
#define HDIM 128
#define WDIM 128
#define HID 64

typedef uint32_t u32;
typedef uint16_t u16;

// layer-0 output h (NHWC fp32); consumed by attention pass 0; reused for h1
__device__ __align__(16) float g_buf0[BATCH * HDIM * WDIM * HID];
// padded f16 activations for layer-1 conv: [16][130][130][64]
__device__ __align__(16) __half g_h16[BATCH * 130 * 130 * HID];
// f16 layer-1 weights: [tap 9][gate*64+oc 320][cin 64]
__device__ __align__(16) __half g_w1h[9 * 320 * 64];
// f16 attention weights: qkv hi only [192][64]; proj hi/lo [64][64]
__device__ __align__(16) __half g_wqh[2][192 * 64];
__device__ __align__(16) __half g_wph[2][64 * 64];
__device__ __align__(16) __half g_wpl[2][64 * 64];

__device__ __forceinline__ float sigm(float v) {
    return __fdividef(1.0f, 1.0f + __expf(-v));
}
__device__ __forceinline__ float ftanh(float v) {
    return 1.0f - __fdividef(2.0f, __expf(2.0f * v) + 1.0f);
}

// ===================== sm_80+ tensor helpers (no 'a' target) ================
__device__ __forceinline__ u32 smem_u32(const void* p) {
    u32 a;
    asm("{ .reg .u64 t; cvta.to.shared.u64 t, %1; cvt.u32.u64 %0, t; }"
        : "=r"(a) : "l"(p));
    return a;
}
__device__ __forceinline__ void cp16(u32 dst, const void* src) {
    asm volatile("cp.async.cg.shared.global [%0], [%1], 16;" :: "r"(dst), "l"(src));
}
#define CPASYNC_COMMIT() asm volatile("cp.async.commit_group;" ::: "memory")
#define CPASYNC_WAIT0()  asm volatile("cp.async.wait_group 0;" ::: "memory")

__device__ __forceinline__ void ldsm4(u32* r, u32 a) {
    asm volatile("ldmatrix.sync.aligned.m8n8.x4.shared.b16 {%0,%1,%2,%3}, [%4];"
                 : "=r"(r[0]), "=r"(r[1]), "=r"(r[2]), "=r"(r[3]) : "r"(a));
}
__device__ __forceinline__ void mma16816(float* c, const u32* a, u32 b0, u32 b1) {
    asm volatile(
        "mma.sync.aligned.m16n8k16.row.col.f32.f16.f16.f32 "
        "{%0,%1,%2,%3}, {%4,%5,%6,%7}, {%8,%9}, {%0,%1,%2,%3};"
        : "+f"(c[0]), "+f"(c[1]), "+f"(c[2]), "+f"(c[3])
        : "r"(a[0]), "r"(a[1]), "r"(a[2]), "r"(a[3]), "r"(b0), "r"(b1));
}
__device__ __forceinline__ u32 pk2(float lo, float hi) {   // {lo | hi<<16}
    u32 r;
    asm("cvt.rn.f16x2.f32 %0, %1, %2;" : "=r"(r) : "f"(hi), "f"(lo));
    return r;
}
// f16 hi/lo split of a float pair
__device__ __forceinline__ void split2(float a, float b, u32& hi, u32& lo) {
    __half ha = __float2half_rn(a), hb = __float2half_rn(b);
    hi = ((u32)__half_as_ushort(hb) << 16) | (u32)__half_as_ushort(ha);
    lo = pk2(a - __half2float(ha), b - __half2float(hb));
}
__device__ __forceinline__ void sts32(u32 addr, u32 v) {
    asm volatile("st.shared.b32 [%0], %1;" :: "r"(addr), "r"(v));
}
__device__ __forceinline__ void sts16(u32 addr, float v) {
    u16 b = __half_as_ushort(__float2half_rn(v));
    asm volatile("st.shared.b16 [%0], %1;" :: "r"(addr), "h"(b) : "memory");
}

// ---------------------------------------------------------------------------
// Prep work sizes (executed by extra blocks of the layer0 launch)
// ---------------------------------------------------------------------------
#define PREP_A (9 * 320 * 64)          // 184320
#define PREP_B (BATCH * 130 * 130)     // 270400
#define PREP_C (192 * 64)              // 12288
#define PREP_D (64 * 64)               // 4096
#define PREP_TOTAL (PREP_A + PREP_B + PREP_C + PREP_D)
#define PREP_BLOCKS ((PREP_TOTAL + 255) / 256)

__device__ __forceinline__ void do_prep(
    int idx,
    const float* __restrict__ cw, const float* __restrict__ pxw,
    const float* __restrict__ pyw,
    const float* __restrict__ q0, const float* __restrict__ p0,
    const float* __restrict__ q1, const float* __restrict__ p1) {
    if (idx < PREP_A) {
        int tap = idx / (320 * 64);
        int rem = idx % (320 * 64);
        int r = rem / 64, cin = rem % 64;
        int g = r >> 6, n = r & 63;
        float v;
        if (g == 0)      v = cw[(n * 128 + cin) * 9 + tap];
        else if (g == 1) v = cw[((128 + n) * 128 + cin) * 9 + tap];
        else if (g == 2) v = cw[((192 + n) * 128 + cin) * 9 + tap];
        else if (g == 3) v = pxw[(n * 64 + cin) * 9 + tap];
        else             v = pyw[(n * 64 + cin) * 9 + tap];
        g_w1h[idx] = __float2half_rn(v);
        return;
    }
    idx -= PREP_A;
    if (idx < PREP_B) {
        int bp = idx % (130 * 130);
        int yy = bp / 130, xx = bp % 130;
        if (yy == 0 || yy == 129 || xx == 0 || xx == 129) {
            uint4* d = (uint4*)(g_h16 + (size_t)idx * 64);
            uint4 z = {0, 0, 0, 0};
#pragma unroll
            for (int i = 0; i < 8; i++) d[i] = z;
        }
        return;
    }
    idx -= PREP_B;
    if (idx < PREP_C) {
        g_wqh[0][idx] = __float2half_rn(q0[idx]);
        g_wqh[1][idx] = __float2half_rn(q1[idx]);
        return;
    }
    idx -= PREP_C;
    if (idx < PREP_D) {
        float v0 = p0[idx], v1 = p1[idx];
        __half h0 = __float2half_rn(v0), h1 = __float2half_rn(v1);
        g_wph[0][idx] = h0; g_wpl[0][idx] = __float2half_rn(v0 - __half2float(h0));
        g_wph[1][idx] = h1; g_wpl[1][idx] = __float2half_rn(v1 - __half2float(h1));
    }
}

// ---------------------------------------------------------------------------
// Layer 0 fused gates + prep piggyback blocks.
// ---------------------------------------------------------------------------
__global__ __launch_bounds__(256) void layer0_gates(
    const float* __restrict__ x, const float* __restrict__ cw,
    const float* __restrict__ cb, const float* __restrict__ pxw,
    const float* __restrict__ pyw,
    const float* __restrict__ cw1, const float* __restrict__ pxw1,
    const float* __restrict__ pyw1,
    const float* __restrict__ q0, const float* __restrict__ p0,
    const float* __restrict__ q1, const float* __restrict__ p1) {
    __shared__ float s_w[64 * 48];
    __shared__ float s_b[3][64];
    __shared__ float s_out[256 * 20];
    int tid = threadIdx.x;

    if (blockIdx.x >= 1024) {
        int idx = (blockIdx.x - 1024) * 256 + tid;
        do_prep(idx, cw1, pxw1, pyw1, q0, p0, q1, p1);
        return;
    }

    for (int i = tid; i < 64 * 45; i += 256) {
        int c = i / 45, j = i % 45;
        int g = j / 9, tap = j % 9;
        float v;
        if (g == 0)      v = cw[c * 585 + tap];
        else if (g == 1) v = cw[(128 + c) * 585 + tap];
        else if (g == 2) v = cw[(192 + c) * 585 + tap];
        else if (g == 3) v = pxw[c * 9 + tap];
        else             v = pyw[c * 9 + tap];
        s_w[c * 48 + j] = v;
    }
    if (tid < 64) {
        s_b[0][tid] = cb[tid];
        s_b[1][tid] = cb[128 + tid];
        s_b[2][tid] = cb[192 + tid];
    }
    __syncthreads();

    int p = blockIdx.x * 256 + tid;
    int b = p >> 14, y = (p >> 7) & 127, xc = p & 127;
    float pv[9];
#pragma unroll
    for (int ky = 0; ky < 3; ky++)
#pragma unroll
        for (int kx = 0; kx < 3; kx++) {
            int gy = y + ky - 1, gx = xc + kx - 1;
            pv[ky * 3 + kx] = (gy >= 0 && gy < 128 && gx >= 0 && gx < 128)
                                  ? x[(b << 14) + gy * 128 + gx] : 0.0f;
        }

#pragma unroll 1
    for (int chunk = 0; chunk < 4; chunk++) {
        float4 ov;
#pragma unroll
        for (int cc = 0; cc < 16; cc++) {
            int c = chunk * 16 + cc;
            float wv[48];
            const float4* w4 = (const float4*)(s_w + c * 48);
#pragma unroll
            for (int q = 0; q < 12; q++) {
                float4 t4 = w4[q];
                wv[q * 4 + 0] = t4.x; wv[q * 4 + 1] = t4.y;
                wv[q * 4 + 2] = t4.z; wv[q * 4 + 3] = t4.w;
            }
            float aci = 0.f, aco = 0.f, acg = 0.f, apx = 0.f, apy = 0.f;
#pragma unroll
            for (int tap = 0; tap < 9; tap++) {
                float a = pv[tap];
                aci += a * wv[tap];
                aco += a * wv[9 + tap];
                acg += a * wv[18 + tap];
                apx += a * wv[27 + tap];
                apy += a * wv[36 + tap];
            }
            float ig = sigm(aci + apx + s_b[0][c]);
            float og = sigm(aco + apy + s_b[1][c]);
            float gg = ftanh(acg + apy + s_b[2][c]);
            float r = og * ftanh(ig * gg);
            int e = cc & 3;
            if (e == 0) ov.x = r; else if (e == 1) ov.y = r;
            else if (e == 2) ov.z = r;
            else {
                ov.w = r;
                *(float4*)(s_out + tid * 20 + (cc >> 2) * 4) = ov;
            }
        }
        __syncthreads();
#pragma unroll
        for (int it = 0; it < 4; it++) {
            int i = it * 256 + tid;
            int pp = i >> 2, k = i & 3;
            float4 v4 = *(const float4*)(s_out + pp * 20 + k * 4);
            *(float4*)(g_buf0 +
                       ((size_t)(blockIdx.x * 256 + pp)) * 64 + chunk * 16 + k * 4) = v4;
        }
        __syncthreads();
    }
}

// ---------------------------------------------------------------------------
// Window attention on mma.sync, 8 warps/window. Compensation kept on
// Q/K/V/P/O activations (phase 2) and proj (x-lo + w-lo); QKV now 1-term
// (Ah*Bh only): x-lo and wq-lo dropped there per measured error budget.
// ---------------------------------------------------------------------------
#define AT_XH 0
#define AT_XL 8192
#define AT_QH 16384
#define AT_QL 24576
#define AT_KH 32768
#define AT_KL 40960
#define AT_VTH 49152
#define AT_VTL 57344
#define AT_WQH 65536
#define AT_RED 90112
#define AT_SMEM 90624

__global__ __launch_bounds__(256, 2) void win_attn_tc(
    int layer, const float* __restrict__ projb,
    const float* __restrict__ outw, const float* __restrict__ outb,
    float* __restrict__ out, int to_h16) {
    extern __shared__ char smem[];
    u32 sb = smem_u32(smem);
    int tid = threadIdx.x, lane = tid & 31, w = tid >> 5;
    int wid = blockIdx.x;
    int b = wid >> 8, wy = (wid >> 4) & 15, wx = wid & 15;
    int base = ((b * 128 + wy * 8) * 128 + wx * 8) * 64;

    // ---- stage qkv weights (hi only) ----
    if (tid < 192) {
        int r = tid;
        const __half* sh = g_wqh[layer] + r * 64;
        u32 row = (u32)r * 128, sw = (u32)((r & 7) << 4);
#pragma unroll
        for (int i = 0; i < 8; i++)
            cp16(sb + AT_WQH + ((row + i * 16) ^ sw), (const char*)sh + i * 16);
    }
    CPASYNC_COMMIT();
    {
        int row = tid >> 2, q = tid & 3;              // token row, 16-col quarter
        int ty = row >> 3, tx = row & 7;
        const float* src = g_buf0 + base + (ty * 128 + tx) * 64 + q * 16;
        u32 sw = (u32)((row & 7) << 4);
#pragma unroll
        for (int j = 0; j < 4; j++) {
            float4 a = *(const float4*)(src + j * 4);
            u32 byte0 = (u32)(row * 128 + q * 32 + j * 8);
            u32 h01, l01, h23, l23;
            split2(a.x, a.y, h01, l01);
            split2(a.z, a.w, h23, l23);
            sts32(sb + AT_XH + (byte0 ^ sw), h01);
            sts32(sb + AT_XL + (byte0 ^ sw), l01);
            sts32(sb + AT_XH + ((byte0 + 4) ^ sw), h23);
            sts32(sb + AT_XL + ((byte0 + 4) ^ sw), l23);
        }
    }
    CPASYNC_WAIT0();
    __syncthreads();

    // lane-invariant ldsm address pieces
    int aRow = (lane & 7) + 8 * ((lane >> 3) & 1);
    u32 aKl = (u32)(16 * (lane >> 4));
    int bRow = ((lane >> 4) & 1) * 8 + (lane & 7);
    u32 bKl = (u32)(((lane >> 3) & 1) * 16);
    int g = lane >> 2, t = lane & 3;

    // ---- phase 1: QKV GEMM (1-term: Ah*Bh). warp = (ocg, mh) ----
    {
        int ocg = w >> 1, mh = w & 1;
        float c[2][6][4];
#pragma unroll
        for (int mtl = 0; mtl < 2; mtl++)
#pragma unroll
            for (int nt = 0; nt < 6; nt++)
#pragma unroll
                for (int e = 0; e < 4; e++) c[mtl][nt][e] = 0.0f;

#pragma unroll
        for (int ks = 0; ks < 4; ks++) {
            u32 ah[2][4];
#pragma unroll
            for (int mtl = 0; mtl < 2; mtl++) {
                u32 ar = (u32)((mh * 2 + mtl) * 16 + aRow);
                u32 off = ar * 128 + (u32)(ks * 32) + aKl;
                u32 sw = ((ar & 7) << 4);
                ldsm4(ah[mtl], sb + AT_XH + (off ^ sw));
            }
#pragma unroll
            for (int np = 0; np < 3; np++) {
                u32 bh[4];
                u32 nr = (u32)(ocg * 48 + np * 16 + bRow);
                u32 off = nr * 128 + (u32)(ks * 32) + bKl;
                u32 sw = ((nr & 7) << 4);
                ldsm4(bh, sb + AT_WQH + (off ^ sw));
#pragma unroll
                for (int mtl = 0; mtl < 2; mtl++) {
                    mma16816(c[mtl][np * 2], ah[mtl], bh[0], bh[1]);
                    mma16816(c[mtl][np * 2 + 1], ah[mtl], bh[2], bh[3]);
                }
            }
        }
        // store Q (x0.25), K, V^T as f16 hi/lo
#pragma unroll
        for (int mtl = 0; mtl < 2; mtl++) {
            int mt = (w & 1) * 2 + mtl;
#pragma unroll
            for (int nt = 0; nt < 6; nt++) {
                int nc = ocg * 48 + nt * 8 + t * 2;
                int r0 = mt * 16 + g, r1 = r0 + 8;
                float v0 = c[mtl][nt][0], v1 = c[mtl][nt][1];
                float v2 = c[mtl][nt][2], v3 = c[mtl][nt][3];
                u32 sw0 = ((u32)(r0 & 7) << 4), sw1 = ((u32)(r1 & 7) << 4);
                if (nc < 64) {
                    u32 h01, l01, h23, l23;
                    split2(v0 * 0.25f, v1 * 0.25f, h01, l01);
                    split2(v2 * 0.25f, v3 * 0.25f, h23, l23);
                    u32 o0 = ((u32)(r0 * 128 + nc * 2)) ^ sw0;
                    u32 o1 = ((u32)(r1 * 128 + nc * 2)) ^ sw1;
                    sts32(sb + AT_QH + o0, h01); sts32(sb + AT_QL + o0, l01);
                    sts32(sb + AT_QH + o1, h23); sts32(sb + AT_QL + o1, l23);
                } else if (nc < 128) {
                    int kc = nc - 64;
                    u32 h01, l01, h23, l23;
                    split2(v0, v1, h01, l01);
                    split2(v2, v3, h23, l23);
                    u32 o0 = ((u32)(r0 * 128 + kc * 2)) ^ sw0;
                    u32 o1 = ((u32)(r1 * 128 + kc * 2)) ^ sw1;
                    sts32(sb + AT_KH + o0, h01); sts32(sb + AT_KL + o0, l01);
                    sts32(sb + AT_KH + o1, h23); sts32(sb + AT_KL + o1, l23);
                } else {
                    int d0 = nc - 128, d1 = d0 + 1;
                    u32 s0 = (u32)((d0 & 7) << 4), s1 = (u32)((d1 & 7) << 4);
                    float vv[4] = {v0, v1, v2, v3};
                    int dd[4] = {d0, d1, d0, d1};
                    int rr[4] = {r0, r0, r1, r1};
                    u32 ss[4] = {s0, s1, s0, s1};
#pragma unroll
                    for (int e = 0; e < 4; e++) {
                        __half h = __float2half_rn(vv[e]);
                        float rl = vv[e] - __half2float(h);
                        u32 off = ((u32)(dd[e] * 128 + rr[e] * 2)) ^ ss[e];
                        sts16(sb + AT_VTH + off, vv[e]);
                        sts16(sb + AT_VTL + off, rl);
                    }
                }
            }
        }
    }
    __syncthreads();

    // ---- phase 2: attention, warp = (head, mt-half) ----
    {
        int h = w >> 1, mh = w & 1;
        u32 kbh[4][4], kbl[4][4], vbh[4][4], vbl[4][4];
#pragma unroll
        for (int np = 0; np < 4; np++) {
            u32 nr = (u32)(np * 16 + bRow);
            u32 off = nr * 128 + (u32)(h * 32) + bKl;
            u32 sw = ((nr & 7) << 4);
            ldsm4(kbh[np], sb + AT_KH + (off ^ sw));
            ldsm4(kbl[np], sb + AT_KL + (off ^ sw));
        }
#pragma unroll
        for (int ks = 0; ks < 4; ks++) {
            u32 nr = (u32)(h * 16 + bRow);
            u32 off = nr * 128 + (u32)(ks * 32) + bKl;
            u32 sw = ((nr & 7) << 4);
            ldsm4(vbh[ks], sb + AT_VTH + (off ^ sw));
            ldsm4(vbl[ks], sb + AT_VTL + (off ^ sw));
        }
        __syncthreads();   // all warps hold K/V fragments; vt planes now free
        // stage proj weights hi/lo into the vt planes (overlap with compute)
        if (tid < 128) {
            int r = tid & 63;
            const __half* src = (tid < 64) ? (g_wph[layer] + r * 64)
                                           : (g_wpl[layer] + r * 64);
            u32 dstb = (tid < 64) ? (sb + AT_VTH) : (sb + AT_VTL);
            u32 row = (u32)r * 128, sw = (u32)((r & 7) << 4);
#pragma unroll
            for (int i = 0; i < 8; i++)
                cp16(dstb + ((row + i * 16) ^ sw), (const char*)src + i * 16);
        }
        CPASYNC_COMMIT();

#pragma unroll
        for (int mtl = 0; mtl < 2; mtl++) {
            int mt = mh * 2 + mtl;
            u32 aqh[4], aql[4];
            u32 ar = (u32)(mt * 16 + aRow);
            u32 off = ar * 128 + (u32)(h * 32) + aKl;
            u32 sw = ((ar & 7) << 4);
            ldsm4(aqh, sb + AT_QH + (off ^ sw));
            ldsm4(aql, sb + AT_QL + (off ^ sw));

            float s[8][4];
#pragma unroll
            for (int nt = 0; nt < 8; nt++)
#pragma unroll
                for (int e = 0; e < 4; e++) s[nt][e] = 0.0f;
#pragma unroll
            for (int np = 0; np < 4; np++) {
                mma16816(s[np * 2], aqh, kbh[np][0], kbh[np][1]);
                mma16816(s[np * 2], aql, kbh[np][0], kbh[np][1]);
                mma16816(s[np * 2], aqh, kbl[np][0], kbl[np][1]);
                mma16816(s[np * 2 + 1], aqh, kbh[np][2], kbh[np][3]);
                mma16816(s[np * 2 + 1], aql, kbh[np][2], kbh[np][3]);
                mma16816(s[np * 2 + 1], aqh, kbl[np][2], kbl[np][3]);
            }
            // softmax rows (mt*16+g) and (+8)
            float m0 = -1e30f, m1 = -1e30f;
#pragma unroll
            for (int nt = 0; nt < 8; nt++) {
                m0 = fmaxf(m0, fmaxf(s[nt][0], s[nt][1]));
                m1 = fmaxf(m1, fmaxf(s[nt][2], s[nt][3]));
            }
            m0 = fmaxf(m0, __shfl_xor_sync(0xffffffff, m0, 1));
            m0 = fmaxf(m0, __shfl_xor_sync(0xffffffff, m0, 2));
            m1 = fmaxf(m1, __shfl_xor_sync(0xffffffff, m1, 1));
            m1 = fmaxf(m1, __shfl_xor_sync(0xffffffff, m1, 2));
            float s0 = 0.f, s1 = 0.f;
#pragma unroll
            for (int nt = 0; nt < 8; nt++) {
                s[nt][0] = __expf(s[nt][0] - m0); s0 += s[nt][0];
                s[nt][1] = __expf(s[nt][1] - m0); s0 += s[nt][1];
                s[nt][2] = __expf(s[nt][2] - m1); s1 += s[nt][2];
                s[nt][3] = __expf(s[nt][3] - m1); s1 += s[nt][3];
            }
            s0 += __shfl_xor_sync(0xffffffff, s0, 1);
            s0 += __shfl_xor_sync(0xffffffff, s0, 2);
            s1 += __shfl_xor_sync(0xffffffff, s1, 1);
            s1 += __shfl_xor_sync(0xffffffff, s1, 2);
            float i0 = 1.0f / s0, i1 = 1.0f / s1;

            float o[2][4];
#pragma unroll
            for (int nt = 0; nt < 2; nt++)
#pragma unroll
                for (int e = 0; e < 4; e++) o[nt][e] = 0.0f;
#pragma unroll
            for (int ks = 0; ks < 4; ks++) {
                u32 ph[4], pl[4];
                split2(s[2 * ks][0], s[2 * ks][1], ph[0], pl[0]);
                split2(s[2 * ks][2], s[2 * ks][3], ph[1], pl[1]);
                split2(s[2 * ks + 1][0], s[2 * ks + 1][1], ph[2], pl[2]);
                split2(s[2 * ks + 1][2], s[2 * ks + 1][3], ph[3], pl[3]);
                mma16816(o[0], ph, vbh[ks][0], vbh[ks][1]);
                mma16816(o[0], pl, vbh[ks][0], vbh[ks][1]);
                mma16816(o[0], ph, vbl[ks][0], vbl[ks][1]);
                mma16816(o[1], ph, vbh[ks][2], vbh[ks][3]);
                mma16816(o[1], pl, vbh[ks][2], vbh[ks][3]);
                mma16816(o[1], ph, vbl[ks][2], vbl[ks][3]);
            }
            // scale + store O hi/lo to x planes
            int r0 = mt * 16 + g, r1 = r0 + 8;
            u32 sw0 = ((u32)(r0 & 7) << 4), sw1 = ((u32)(r1 & 7) << 4);
#pragma unroll
            for (int nt = 0; nt < 2; nt++) {
                int dc = h * 16 + nt * 8 + t * 2;
                u32 h01, l01, h23, l23;
                split2(o[nt][0] * i0, o[nt][1] * i0, h01, l01);
                split2(o[nt][2] * i1, o[nt][3] * i1, h23, l23);
                u32 o0 = ((u32)(r0 * 128 + dc * 2)) ^ sw0;
                u32 o1 = ((u32)(r1 * 128 + dc * 2)) ^ sw1;
                sts32(sb + AT_XH + o0, h01); sts32(sb + AT_XL + o0, l01);
                sts32(sb + AT_XH + o1, h23); sts32(sb + AT_XL + o1, l23);
            }
        }
    }
    CPASYNC_WAIT0();
    __syncthreads();

    // ---- phase 3: proj GEMM (3-term), warp = (m-tile, n-half) ----
    {
        int mtile = w >> 1, nh = w & 1;
        float c[4][4];
#pragma unroll
        for (int nt = 0; nt < 4; nt++)
#pragma unroll
            for (int e = 0; e < 4; e++) c[nt][e] = 0.0f;
#pragma unroll
        for (int ks = 0; ks < 4; ks++) {
            u32 ah[4], al[4];
            u32 ar = (u32)(mtile * 16 + aRow);
            u32 off = ar * 128 + (u32)(ks * 32) + aKl;
            u32 sw = ((ar & 7) << 4);
            ldsm4(ah, sb + AT_XH + (off ^ sw));
            ldsm4(al, sb + AT_XL + (off ^ sw));
#pragma unroll
            for (int npl = 0; npl < 2; npl++) {
                int np = nh * 2 + npl;
                u32 bh[4], bl[4];
                u32 nr = (u32)(np * 16 + bRow);
                u32 boff = nr * 128 + (u32)(ks * 32) + bKl;
                u32 bsw = ((nr & 7) << 4);
                ldsm4(bh, sb + AT_VTH + (boff ^ bsw));
                ldsm4(bl, sb + AT_VTL + (boff ^ bsw));
                mma16816(c[npl * 2], ah, bh[0], bh[1]);
                mma16816(c[npl * 2], al, bh[0], bh[1]);
                mma16816(c[npl * 2], ah, bl[0], bl[1]);
                mma16816(c[npl * 2 + 1], ah, bh[2], bh[3]);
                mma16816(c[npl * 2 + 1], al, bh[2], bh[3]);
                mma16816(c[npl * 2 + 1], ah, bl[2], bl[3]);
            }
        }
        if (to_h16) {
#pragma unroll
            for (int ntl = 0; ntl < 4; ntl++) {
                int nt = nh * 4 + ntl;
                int cc = nt * 8 + t * 2;
                float b0 = __ldg(projb + cc), b1 = __ldg(projb + cc + 1);
#pragma unroll
                for (int rh = 0; rh < 2; rh++) {
                    int tok = mtile * 16 + g + rh * 8;
                    int ty = tok >> 3, tx = tok & 7;
                    float v0 = c[ntl][rh * 2] + b0, v1 = c[ntl][rh * 2 + 1] + b1;
                    int gy = wy * 8 + ty, gx = wx * 8 + tx;
                    __half* dst = g_h16 +
                        ((size_t)((b * 130 + gy + 1) * 130 + gx + 1)) * 64 + cc;
                    *(__half2*)dst = __floats2half2_rn(v0, v1);
                }
            }
        } else {
            float* s_red = (float*)(smem + AT_RED);    // [4 mtile][2 nh][8 g][2 rh]
            float acc0 = 0.0f, acc1 = 0.0f;
#pragma unroll
            for (int ntl = 0; ntl < 4; ntl++) {
                int cc = (nh * 4 + ntl) * 8 + t * 2;
                float b0 = __ldg(projb + cc), b1 = __ldg(projb + cc + 1);
                float w0 = __ldg(outw + cc), w1 = __ldg(outw + cc + 1);
                acc0 += (c[ntl][0] + b0) * w0 + (c[ntl][1] + b1) * w1;
                acc1 += (c[ntl][2] + b0) * w0 + (c[ntl][3] + b1) * w1;
            }
            acc0 += __shfl_xor_sync(0xffffffff, acc0, 1);
            acc0 += __shfl_xor_sync(0xffffffff, acc0, 2);
            acc1 += __shfl_xor_sync(0xffffffff, acc1, 1);
            acc1 += __shfl_xor_sync(0xffffffff, acc1, 2);
            if (t == 0) {
                s_red[((mtile * 2 + nh) * 8 + g) * 2 + 0] = acc0;
                s_red[((mtile * 2 + nh) * 8 + g) * 2 + 1] = acc1;
            }
            __syncthreads();
            if (tid < 64) {
                int mt2 = tid >> 4, g2 = (tid >> 1) & 7, rh2 = tid & 1;
                float v = s_red[((mt2 * 2 + 0) * 8 + g2) * 2 + rh2] +
                          s_red[((mt2 * 2 + 1) * 8 + g2) * 2 + rh2] + __ldg(outb);
                int tok = mt2 * 16 + g2 + rh2 * 8;
                int ty = tok >> 3, tx = tok & 7;
                int gy = wy * 8 + ty, gx = wx * 8 + tx;
                out[(b * 128 + gy) * 128 + gx] = v;
            }
        }
    }
}

// ---------------------------------------------------------------------------
// Layer 1 conv on mma.sync (round-10 version: full row, 512 thr, 2-stage B)
// ---------------------------------------------------------------------------
#define L1_A_OFF 0
#define L1_A_BYTES (390 * 128)
#define L1_B0 L1_A_BYTES
#define L1_B_BYTES (320 * 128)
#define L1_B1 (L1_B0 + L1_B_BYTES)
#define L1_SMEM_TOTAL (L1_B1 + L1_B_BYTES)   // 131840

__device__ __forceinline__ void l1_load_B(u32 sB, int tap, int tid) {
    if (tid < 320) {
        const __half* src = g_w1h + (size_t)(tap * 320 + tid) * 64;
        u32 row = tid * 128;
        u32 sw = (u32)((tid & 7) << 4);
#pragma unroll
        for (int i = 0; i < 8; i++)
            cp16(sB + ((row + i * 16) ^ sw), (const char*)src + i * 16);
    }
}

__global__ __launch_bounds__(512, 1) void layer1_tc(const float* __restrict__ cb) {
    extern __shared__ char smem[];
    u32 sb = smem_u32(smem);
    int tid = threadIdx.x, lane = tid & 31, warp = tid >> 5;
    int wm = warp & 3, wn = warp >> 2;
    int tile = blockIdx.x;
    int b = tile >> 7, y = tile & 127;

    if (tid < 390) {
        int rowIdx = tid / 130, col = tid % 130;
        const __half* src = g_h16 +
            ((size_t)((b * 130 + y + rowIdx) * 130 + col)) * 64;
        u32 row = (u32)tid * 128;
        u32 sw = (u32)((tid & 7) << 4);
#pragma unroll
        for (int i = 0; i < 8; i++)
            cp16(sb + L1_A_OFF + ((row + i * 16) ^ sw), (const char*)src + i * 16);
    }
    l1_load_B(sb + L1_B0, 0, tid);
    CPASYNC_COMMIT();
    CPASYNC_WAIT0();
    __syncthreads();

    float c[2][5][2][4];
#pragma unroll
    for (int mi = 0; mi < 2; mi++)
#pragma unroll
        for (int g5 = 0; g5 < 5; g5++)
#pragma unroll
            for (int nt = 0; nt < 2; nt++)
#pragma unroll
                for (int e = 0; e < 4; e++) c[mi][g5][nt][e] = 0.0f;

    int arow = wm * 32 + (lane & 7) + 8 * ((lane >> 3) & 1);
    u32 aklane = (u32)(16 * (lane >> 4));
    u32 bkl = (u32)(((lane >> 3) & 1) * 16);
    int bnrow_base = wn * 16 + ((lane >> 4) & 1) * 8 + (lane & 7);
    u32 bswz = (u32)((lane & 7) << 4);

#pragma unroll 1
    for (int tap = 0; tap < 9; tap++) {
        u32 Bb = sb + ((tap & 1) ? L1_B1 : L1_B0);
        if (tap < 8) {
            l1_load_B(sb + ((tap & 1) ? L1_B0 : L1_B1), tap + 1, tid);
            CPASYNC_COMMIT();
        }
        int dy = tap / 3, dx = tap % 3;
        int br0 = dy * 130 + arow + dx;
#pragma unroll
        for (int ks = 0; ks < 4; ks++) {
            u32 a[2][4];
#pragma unroll
            for (int mi = 0; mi < 2; mi++) {
                u32 br = (u32)(br0 + mi * 16);
                u32 off = br * 128 + (u32)(ks * 32) + aklane;
                ldsm4(a[mi], sb + L1_A_OFF + (off ^ ((br & 7) << 4)));
            }
#pragma unroll
            for (int g5 = 0; g5 < 5; g5++) {
                u32 bfr[4];
                u32 nrow = (u32)(g5 * 64 + bnrow_base);
                u32 off = nrow * 128 + (u32)(ks * 32) + bkl;
                ldsm4(bfr, Bb + (off ^ bswz));
#pragma unroll
                for (int mi = 0; mi < 2; mi++) {
                    mma16816(c[mi][g5][0], a[mi], bfr[0], bfr[1]);
                    mma16816(c[mi][g5][1], a[mi], bfr[2], bfr[3]);
                }
            }
        }
        if (tap < 8) { CPASYNC_WAIT0(); }
        __syncthreads();
    }

    int q = lane & 3, gr = lane >> 2;
    int ocB = wn * 16;
#pragma unroll
    for (int mi = 0; mi < 2; mi++) {
#pragma unroll
        for (int rh = 0; rh < 2; rh++) {
            int x = wm * 32 + mi * 16 + gr + rh * 8;
            float* orow = g_buf0 + ((size_t)((b * 128 + y) * 128 + x)) * 64;
#pragma unroll
            for (int nt = 0; nt < 2; nt++) {
#pragma unroll
                for (int e = 0; e < 2; e++) {
                    int oc = ocB + nt * 8 + q * 2 + e;
                    int ai = rh * 2 + e;
                    float ci = c[mi][0][nt][ai];
                    float co = c[mi][1][nt][ai];
                    float cg = c[mi][2][nt][ai];
                    float px = c[mi][3][nt][ai];
                    float py = c[mi][4][nt][ai];
                    float ig = sigm(ci + px + __ldg(cb + oc));
                    float og = sigm(co + py + __ldg(cb + 128 + oc));
                    float gg = ftanh(cg + py + __ldg(cb + 192 + oc));
                    orow[oc] = og * ftanh(ig * gg);
                }
            }
        }
    }
}

// ---------------------------------------------------------------------------
extern "C" void kernel_launch(void* const* d_in, const int* in_sizes, int n_in,
                              void* d_out, int out_size) {
    const float* x      = (const float*)d_in[0];
    const float* cw0    = (const float*)d_in[1];
    const float* cb0    = (const float*)d_in[2];
    const float* pxw0   = (const float*)d_in[3];
    const float* pyw0   = (const float*)d_in[4];
    const float* qkvw0  = (const float*)d_in[5];
    const float* projw0 = (const float*)d_in[6];
    const float* projb0 = (const float*)d_in[7];
    const float* cw1    = (const float*)d_in[8];
    const float* cb1    = (const float*)d_in[9];
    const float* pxw1   = (const float*)d_in[10];
    const float* pyw1   = (const float*)d_in[11];
    const float* qkvw1  = (const float*)d_in[12];
    const float* projw1 = (const float*)d_in[13];
    const float* projb1 = (const float*)d_in[14];
    const float* outw   = (const float*)d_in[15];
    const float* outb   = (const float*)d_in[16];
    float* out = (float*)d_out;

    cudaFuncSetAttribute(win_attn_tc, cudaFuncAttributeMaxDynamicSharedMemorySize,
                         AT_SMEM);
    cudaFuncSetAttribute(layer1_tc, cudaFuncAttributeMaxDynamicSharedMemorySize,
                         L1_SMEM_TOTAL);

    // layer0 (blocks 0..1023) + prep piggyback (blocks 1024..)
    layer0_gates<<<1024 + PREP_BLOCKS, 256>>>(x, cw0, cb0, pxw0, pyw0,
                                              cw1, pxw1, pyw1,
                                              qkvw0, projw0, qkvw1, projw1);
    win_attn_tc<<<4096, 256, AT_SMEM>>>(0, projb0, outw, outb, out, 1); // buf0 -> h16
    layer1_tc<<<2048, 512, L1_SMEM_TOTAL>>>(cb1);                       // h16 -> buf0
    win_attn_tc<<<4096, 256, AT_SMEM>>>(1, projb1, outw, outb, out, 0); // buf0 -> out
}

// round 17
// speedup vs baseline: 1.3290x; 1.0227x over previous
#include <cuda_runtime.h>
#include <cuda_fp16.h>
#include <math.h>
#include <stdint.h>

#define BATCH 16
#define HDIM 128
#define WDIM 128
#define HID 64

typedef uint32_t u32;
typedef uint16_t u16;

// layer-0 output h (NHWC fp32); consumed by attention pass 0; reused for h1
__device__ __align__(16) float g_buf0[BATCH * HDIM * WDIM * HID];
// padded f16 activations for layer-1 conv: [16][130][130][64]
__device__ __align__(16) __half g_h16[BATCH * 130 * 130 * HID];
// f16 layer-1 weights: [tap 9][gate*64+oc 320][cin 64]
__device__ __align__(16) __half g_w1h[9 * 320 * 64];
// f16 attention weights: qkv hi only [192][64]; proj hi/lo [64][64]
__device__ __align__(16) __half g_wqh[2][192 * 64];
__device__ __align__(16) __half g_wph[2][64 * 64];
__device__ __align__(16) __half g_wpl[2][64 * 64];

__device__ __forceinline__ float sigm(float v) {
    return __fdividef(1.0f, 1.0f + __expf(-v));
}
__device__ __forceinline__ float ftanh(float v) {
    return 1.0f - __fdividef(2.0f, __expf(2.0f * v) + 1.0f);
}

// ===================== sm_80+ tensor helpers (no 'a' target) ================
__device__ __forceinline__ u32 smem_u32(const void* p) {
    u32 a;
    asm("{ .reg .u64 t; cvta.to.shared.u64 t, %1; cvt.u32.u64 %0, t; }"
        : "=r"(a) : "l"(p));
    return a;
}
__device__ __forceinline__ void cp16(u32 dst, const void* src) {
    asm volatile("cp.async.cg.shared.global [%0], [%1], 16;" :: "r"(dst), "l"(src));
}
#define CPASYNC_COMMIT() asm volatile("cp.async.commit_group;" ::: "memory")
#define CPASYNC_WAIT0()  asm volatile("cp.async.wait_group 0;" ::: "memory")

__device__ __forceinline__ void ldsm4(u32* r, u32 a) {
    asm volatile("ldmatrix.sync.aligned.m8n8.x4.shared.b16 {%0,%1,%2,%3}, [%4];"
                 : "=r"(r[0]), "=r"(r[1]), "=r"(r[2]), "=r"(r[3]) : "r"(a));
}
__device__ __forceinline__ void mma16816(float* c, const u32* a, u32 b0, u32 b1) {
    asm volatile(
        "mma.sync.aligned.m16n8k16.row.col.f32.f16.f16.f32 "
        "{%0,%1,%2,%3}, {%4,%5,%6,%7}, {%8,%9}, {%0,%1,%2,%3};"
        : "+f"(c[0]), "+f"(c[1]), "+f"(c[2]), "+f"(c[3])
        : "r"(a[0]), "r"(a[1]), "r"(a[2]), "r"(a[3]), "r"(b0), "r"(b1));
}
__device__ __forceinline__ u32 pk2(float lo, float hi) {   // {lo | hi<<16}
    u32 r;
    asm("cvt.rn.f16x2.f32 %0, %1, %2;" : "=r"(r) : "f"(hi), "f"(lo));
    return r;
}
// f16 hi/lo split of a float pair
__device__ __forceinline__ void split2(float a, float b, u32& hi, u32& lo) {
    __half ha = __float2half_rn(a), hb = __float2half_rn(b);
    hi = ((u32)__half_as_ushort(hb) << 16) | (u32)__half_as_ushort(ha);
    lo = pk2(a - __half2float(ha), b - __half2float(hb));
}
__device__ __forceinline__ void sts32(u32 addr, u32 v) {
    asm volatile("st.shared.b32 [%0], %1;" :: "r"(addr), "r"(v));
}
__device__ __forceinline__ void sts16(u32 addr, float v) {
    u16 b = __half_as_ushort(__float2half_rn(v));
    asm volatile("st.shared.b16 [%0], %1;" :: "r"(addr), "h"(b) : "memory");
}

// ---------------------------------------------------------------------------
// Prep work sizes (executed by extra blocks of the layer0 launch)
// ---------------------------------------------------------------------------
#define PREP_A (9 * 320 * 64)          // 184320
#define PREP_B (BATCH * 130 * 130)     // 270400
#define PREP_C (192 * 64)              // 12288
#define PREP_D (64 * 64)               // 4096
#define PREP_TOTAL (PREP_A + PREP_B + PREP_C + PREP_D)
#define PREP_BLOCKS ((PREP_TOTAL + 255) / 256)

__device__ __forceinline__ void do_prep(
    int idx,
    const float* __restrict__ cw, const float* __restrict__ pxw,
    const float* __restrict__ pyw,
    const float* __restrict__ q0, const float* __restrict__ p0,
    const float* __restrict__ q1, const float* __restrict__ p1) {
    if (idx < PREP_A) {
        int tap = idx / (320 * 64);
        int rem = idx % (320 * 64);
        int r = rem / 64, cin = rem % 64;
        int g = r >> 6, n = r & 63;
        float v;
        if (g == 0)      v = cw[(n * 128 + cin) * 9 + tap];
        else if (g == 1) v = cw[((128 + n) * 128 + cin) * 9 + tap];
        else if (g == 2) v = cw[((192 + n) * 128 + cin) * 9 + tap];
        else if (g == 3) v = pxw[(n * 64 + cin) * 9 + tap];
        else             v = pyw[(n * 64 + cin) * 9 + tap];
        g_w1h[idx] = __float2half_rn(v);
        return;
    }
    idx -= PREP_A;
    if (idx < PREP_B) {
        int bp = idx % (130 * 130);
        int yy = bp / 130, xx = bp % 130;
        if (yy == 0 || yy == 129 || xx == 0 || xx == 129) {
            uint4* d = (uint4*)(g_h16 + (size_t)idx * 64);
            uint4 z = {0, 0, 0, 0};
#pragma unroll
            for (int i = 0; i < 8; i++) d[i] = z;
        }
        return;
    }
    idx -= PREP_B;
    if (idx < PREP_C) {
        g_wqh[0][idx] = __float2half_rn(q0[idx]);
        g_wqh[1][idx] = __float2half_rn(q1[idx]);
        return;
    }
    idx -= PREP_C;
    if (idx < PREP_D) {
        float v0 = p0[idx], v1 = p1[idx];
        __half h0 = __float2half_rn(v0), h1 = __float2half_rn(v1);
        g_wph[0][idx] = h0; g_wpl[0][idx] = __float2half_rn(v0 - __half2float(h0));
        g_wph[1][idx] = h1; g_wpl[1][idx] = __float2half_rn(v1 - __half2float(h1));
    }
}

// ---------------------------------------------------------------------------
// Layer 0 fused gates + prep piggyback blocks.
// ---------------------------------------------------------------------------
__global__ __launch_bounds__(256) void layer0_gates(
    const float* __restrict__ x, const float* __restrict__ cw,
    const float* __restrict__ cb, const float* __restrict__ pxw,
    const float* __restrict__ pyw,
    const float* __restrict__ cw1, const float* __restrict__ pxw1,
    const float* __restrict__ pyw1,
    const float* __restrict__ q0, const float* __restrict__ p0,
    const float* __restrict__ q1, const float* __restrict__ p1) {
    __shared__ float s_w[64 * 48];
    __shared__ float s_b[3][64];
    __shared__ float s_out[256 * 20];
    int tid = threadIdx.x;

    if (blockIdx.x >= 1024) {
        int idx = (blockIdx.x - 1024) * 256 + tid;
        do_prep(idx, cw1, pxw1, pyw1, q0, p0, q1, p1);
        return;
    }

    for (int i = tid; i < 64 * 45; i += 256) {
        int c = i / 45, j = i % 45;
        int g = j / 9, tap = j % 9;
        float v;
        if (g == 0)      v = cw[c * 585 + tap];
        else if (g == 1) v = cw[(128 + c) * 585 + tap];
        else if (g == 2) v = cw[(192 + c) * 585 + tap];
        else if (g == 3) v = pxw[c * 9 + tap];
        else             v = pyw[c * 9 + tap];
        s_w[c * 48 + j] = v;
    }
    if (tid < 64) {
        s_b[0][tid] = cb[tid];
        s_b[1][tid] = cb[128 + tid];
        s_b[2][tid] = cb[192 + tid];
    }
    __syncthreads();

    int p = blockIdx.x * 256 + tid;
    int b = p >> 14, y = (p >> 7) & 127, xc = p & 127;
    float pv[9];
#pragma unroll
    for (int ky = 0; ky < 3; ky++)
#pragma unroll
        for (int kx = 0; kx < 3; kx++) {
            int gy = y + ky - 1, gx = xc + kx - 1;
            pv[ky * 3 + kx] = (gy >= 0 && gy < 128 && gx >= 0 && gx < 128)
                                  ? x[(b << 14) + gy * 128 + gx] : 0.0f;
        }

#pragma unroll 1
    for (int chunk = 0; chunk < 4; chunk++) {
        float4 ov;
#pragma unroll
        for (int cc = 0; cc < 16; cc++) {
            int c = chunk * 16 + cc;
            float wv[48];
            const float4* w4 = (const float4*)(s_w + c * 48);
#pragma unroll
            for (int q = 0; q < 12; q++) {
                float4 t4 = w4[q];
                wv[q * 4 + 0] = t4.x; wv[q * 4 + 1] = t4.y;
                wv[q * 4 + 2] = t4.z; wv[q * 4 + 3] = t4.w;
            }
            float aci = 0.f, aco = 0.f, acg = 0.f, apx = 0.f, apy = 0.f;
#pragma unroll
            for (int tap = 0; tap < 9; tap++) {
                float a = pv[tap];
                aci += a * wv[tap];
                aco += a * wv[9 + tap];
                acg += a * wv[18 + tap];
                apx += a * wv[27 + tap];
                apy += a * wv[36 + tap];
            }
            float ig = sigm(aci + apx + s_b[0][c]);
            float og = sigm(aco + apy + s_b[1][c]);
            float gg = ftanh(acg + apy + s_b[2][c]);
            float r = og * ftanh(ig * gg);
            int e = cc & 3;
            if (e == 0) ov.x = r; else if (e == 1) ov.y = r;
            else if (e == 2) ov.z = r;
            else {
                ov.w = r;
                *(float4*)(s_out + tid * 20 + (cc >> 2) * 4) = ov;
            }
        }
        __syncthreads();
#pragma unroll
        for (int it = 0; it < 4; it++) {
            int i = it * 256 + tid;
            int pp = i >> 2, k = i & 3;
            float4 v4 = *(const float4*)(s_out + pp * 20 + k * 4);
            *(float4*)(g_buf0 +
                       ((size_t)(blockIdx.x * 256 + pp)) * 64 + chunk * 16 + k * 4) = v4;
        }
        __syncthreads();
    }
}

// ---------------------------------------------------------------------------
// Window attention on mma.sync, 8 warps/window. Compensation retained:
// x-lo in proj, Q-lo in QK, V-lo in PV, O-lo into proj, proj w-lo.
// Dropped (measured budget): QKV x-lo/w-lo, K-lo in QK, P-lo in PV.
// ---------------------------------------------------------------------------
#define AT_XH 0
#define AT_XL 8192
#define AT_QH 16384
#define AT_QL 24576
#define AT_KH 32768
#define AT_KL 40960
#define AT_VTH 49152
#define AT_VTL 57344
#define AT_WQH 65536
#define AT_RED 90112
#define AT_SMEM 90624

__global__ __launch_bounds__(256, 2) void win_attn_tc(
    int layer, const float* __restrict__ projb,
    const float* __restrict__ outw, const float* __restrict__ outb,
    float* __restrict__ out, int to_h16) {
    extern __shared__ char smem[];
    u32 sb = smem_u32(smem);
    int tid = threadIdx.x, lane = tid & 31, w = tid >> 5;
    int wid = blockIdx.x;
    int b = wid >> 8, wy = (wid >> 4) & 15, wx = wid & 15;
    int base = ((b * 128 + wy * 8) * 128 + wx * 8) * 64;

    // ---- stage qkv weights (hi only) ----
    if (tid < 192) {
        int r = tid;
        const __half* sh = g_wqh[layer] + r * 64;
        u32 row = (u32)r * 128, sw = (u32)((r & 7) << 4);
#pragma unroll
        for (int i = 0; i < 8; i++)
            cp16(sb + AT_WQH + ((row + i * 16) ^ sw), (const char*)sh + i * 16);
    }
    CPASYNC_COMMIT();
    {
        int row = tid >> 2, q = tid & 3;              // token row, 16-col quarter
        int ty = row >> 3, tx = row & 7;
        const float* src = g_buf0 + base + (ty * 128 + tx) * 64 + q * 16;
        u32 sw = (u32)((row & 7) << 4);
#pragma unroll
        for (int j = 0; j < 4; j++) {
            float4 a = *(const float4*)(src + j * 4);
            u32 byte0 = (u32)(row * 128 + q * 32 + j * 8);
            u32 h01, l01, h23, l23;
            split2(a.x, a.y, h01, l01);
            split2(a.z, a.w, h23, l23);
            sts32(sb + AT_XH + (byte0 ^ sw), h01);
            sts32(sb + AT_XL + (byte0 ^ sw), l01);
            sts32(sb + AT_XH + ((byte0 + 4) ^ sw), h23);
            sts32(sb + AT_XL + ((byte0 + 4) ^ sw), l23);
        }
    }
    CPASYNC_WAIT0();
    __syncthreads();

    // lane-invariant ldsm address pieces
    int aRow = (lane & 7) + 8 * ((lane >> 3) & 1);
    u32 aKl = (u32)(16 * (lane >> 4));
    int bRow = ((lane >> 4) & 1) * 8 + (lane & 7);
    u32 bKl = (u32)(((lane >> 3) & 1) * 16);
    int g = lane >> 2, t = lane & 3;

    // ---- phase 1: QKV GEMM (1-term: Ah*Bh). warp = (ocg, mh) ----
    {
        int ocg = w >> 1, mh = w & 1;
        float c[2][6][4];
#pragma unroll
        for (int mtl = 0; mtl < 2; mtl++)
#pragma unroll
            for (int nt = 0; nt < 6; nt++)
#pragma unroll
                for (int e = 0; e < 4; e++) c[mtl][nt][e] = 0.0f;

#pragma unroll
        for (int ks = 0; ks < 4; ks++) {
            u32 ah[2][4];
#pragma unroll
            for (int mtl = 0; mtl < 2; mtl++) {
                u32 ar = (u32)((mh * 2 + mtl) * 16 + aRow);
                u32 off = ar * 128 + (u32)(ks * 32) + aKl;
                u32 sw = ((ar & 7) << 4);
                ldsm4(ah[mtl], sb + AT_XH + (off ^ sw));
            }
#pragma unroll
            for (int np = 0; np < 3; np++) {
                u32 bh[4];
                u32 nr = (u32)(ocg * 48 + np * 16 + bRow);
                u32 off = nr * 128 + (u32)(ks * 32) + bKl;
                u32 sw = ((nr & 7) << 4);
                ldsm4(bh, sb + AT_WQH + (off ^ sw));
#pragma unroll
                for (int mtl = 0; mtl < 2; mtl++) {
                    mma16816(c[mtl][np * 2], ah[mtl], bh[0], bh[1]);
                    mma16816(c[mtl][np * 2 + 1], ah[mtl], bh[2], bh[3]);
                }
            }
        }
        // store Q (x0.25), K, V^T as f16 hi/lo
#pragma unroll
        for (int mtl = 0; mtl < 2; mtl++) {
            int mt = (w & 1) * 2 + mtl;
#pragma unroll
            for (int nt = 0; nt < 6; nt++) {
                int nc = ocg * 48 + nt * 8 + t * 2;
                int r0 = mt * 16 + g, r1 = r0 + 8;
                float v0 = c[mtl][nt][0], v1 = c[mtl][nt][1];
                float v2 = c[mtl][nt][2], v3 = c[mtl][nt][3];
                u32 sw0 = ((u32)(r0 & 7) << 4), sw1 = ((u32)(r1 & 7) << 4);
                if (nc < 64) {
                    u32 h01, l01, h23, l23;
                    split2(v0 * 0.25f, v1 * 0.25f, h01, l01);
                    split2(v2 * 0.25f, v3 * 0.25f, h23, l23);
                    u32 o0 = ((u32)(r0 * 128 + nc * 2)) ^ sw0;
                    u32 o1 = ((u32)(r1 * 128 + nc * 2)) ^ sw1;
                    sts32(sb + AT_QH + o0, h01); sts32(sb + AT_QL + o0, l01);
                    sts32(sb + AT_QH + o1, h23); sts32(sb + AT_QL + o1, l23);
                } else if (nc < 128) {
                    int kc = nc - 64;
                    u32 h01, l01, h23, l23;
                    split2(v0, v1, h01, l01);
                    split2(v2, v3, h23, l23);
                    u32 o0 = ((u32)(r0 * 128 + kc * 2)) ^ sw0;
                    u32 o1 = ((u32)(r1 * 128 + kc * 2)) ^ sw1;
                    sts32(sb + AT_KH + o0, h01); sts32(sb + AT_KL + o0, l01);
                    sts32(sb + AT_KH + o1, h23); sts32(sb + AT_KL + o1, l23);
                } else {
                    int d0 = nc - 128, d1 = d0 + 1;
                    u32 s0 = (u32)((d0 & 7) << 4), s1 = (u32)((d1 & 7) << 4);
                    float vv[4] = {v0, v1, v2, v3};
                    int dd[4] = {d0, d1, d0, d1};
                    int rr[4] = {r0, r0, r1, r1};
                    u32 ss[4] = {s0, s1, s0, s1};
#pragma unroll
                    for (int e = 0; e < 4; e++) {
                        __half h = __float2half_rn(vv[e]);
                        float rl = vv[e] - __half2float(h);
                        u32 off = ((u32)(dd[e] * 128 + rr[e] * 2)) ^ ss[e];
                        sts16(sb + AT_VTH + off, vv[e]);
                        sts16(sb + AT_VTL + off, rl);
                    }
                }
            }
        }
    }
    __syncthreads();

    // ---- phase 2: attention, warp = (head, mt-half) ----
    // QK: Qh*Kh + Qlo*Kh (K-lo dropped). PV: Ph*Vh + Ph*Vlo (P-lo dropped).
    {
        int h = w >> 1, mh = w & 1;
        u32 kbh[4][4], vbh[4][4], vbl[4][4];
#pragma unroll
        for (int np = 0; np < 4; np++) {
            u32 nr = (u32)(np * 16 + bRow);
            u32 off = nr * 128 + (u32)(h * 32) + bKl;
            u32 sw = ((nr & 7) << 4);
            ldsm4(kbh[np], sb + AT_KH + (off ^ sw));
        }
#pragma unroll
        for (int ks = 0; ks < 4; ks++) {
            u32 nr = (u32)(h * 16 + bRow);
            u32 off = nr * 128 + (u32)(ks * 32) + bKl;
            u32 sw = ((nr & 7) << 4);
            ldsm4(vbh[ks], sb + AT_VTH + (off ^ sw));
            ldsm4(vbl[ks], sb + AT_VTL + (off ^ sw));
        }
        __syncthreads();   // all warps hold K/V fragments; vt planes now free
        // stage proj weights hi/lo into the vt planes (overlap with compute)
        if (tid < 128) {
            int r = tid & 63;
            const __half* src = (tid < 64) ? (g_wph[layer] + r * 64)
                                           : (g_wpl[layer] + r * 64);
            u32 dstb = (tid < 64) ? (sb + AT_VTH) : (sb + AT_VTL);
            u32 row = (u32)r * 128, sw = (u32)((r & 7) << 4);
#pragma unroll
            for (int i = 0; i < 8; i++)
                cp16(dstb + ((row + i * 16) ^ sw), (const char*)src + i * 16);
        }
        CPASYNC_COMMIT();

#pragma unroll
        for (int mtl = 0; mtl < 2; mtl++) {
            int mt = mh * 2 + mtl;
            u32 aqh[4], aql[4];
            u32 ar = (u32)(mt * 16 + aRow);
            u32 off = ar * 128 + (u32)(h * 32) + aKl;
            u32 sw = ((ar & 7) << 4);
            ldsm4(aqh, sb + AT_QH + (off ^ sw));
            ldsm4(aql, sb + AT_QL + (off ^ sw));

            float s[8][4];
#pragma unroll
            for (int nt = 0; nt < 8; nt++)
#pragma unroll
                for (int e = 0; e < 4; e++) s[nt][e] = 0.0f;
#pragma unroll
            for (int np = 0; np < 4; np++) {
                mma16816(s[np * 2], aqh, kbh[np][0], kbh[np][1]);
                mma16816(s[np * 2], aql, kbh[np][0], kbh[np][1]);
                mma16816(s[np * 2 + 1], aqh, kbh[np][2], kbh[np][3]);
                mma16816(s[np * 2 + 1], aql, kbh[np][2], kbh[np][3]);
            }
            // softmax rows (mt*16+g) and (+8)
            float m0 = -1e30f, m1 = -1e30f;
#pragma unroll
            for (int nt = 0; nt < 8; nt++) {
                m0 = fmaxf(m0, fmaxf(s[nt][0], s[nt][1]));
                m1 = fmaxf(m1, fmaxf(s[nt][2], s[nt][3]));
            }
            m0 = fmaxf(m0, __shfl_xor_sync(0xffffffff, m0, 1));
            m0 = fmaxf(m0, __shfl_xor_sync(0xffffffff, m0, 2));
            m1 = fmaxf(m1, __shfl_xor_sync(0xffffffff, m1, 1));
            m1 = fmaxf(m1, __shfl_xor_sync(0xffffffff, m1, 2));
            float s0 = 0.f, s1 = 0.f;
#pragma unroll
            for (int nt = 0; nt < 8; nt++) {
                s[nt][0] = __expf(s[nt][0] - m0); s0 += s[nt][0];
                s[nt][1] = __expf(s[nt][1] - m0); s0 += s[nt][1];
                s[nt][2] = __expf(s[nt][2] - m1); s1 += s[nt][2];
                s[nt][3] = __expf(s[nt][3] - m1); s1 += s[nt][3];
            }
            s0 += __shfl_xor_sync(0xffffffff, s0, 1);
            s0 += __shfl_xor_sync(0xffffffff, s0, 2);
            s1 += __shfl_xor_sync(0xffffffff, s1, 1);
            s1 += __shfl_xor_sync(0xffffffff, s1, 2);
            float i0 = 1.0f / s0, i1 = 1.0f / s1;

            float o[2][4];
#pragma unroll
            for (int nt = 0; nt < 2; nt++)
#pragma unroll
                for (int e = 0; e < 4; e++) o[nt][e] = 0.0f;
#pragma unroll
            for (int ks = 0; ks < 4; ks++) {
                u32 ph[4];
                ph[0] = pk2(s[2 * ks][0], s[2 * ks][1]);
                ph[1] = pk2(s[2 * ks][2], s[2 * ks][3]);
                ph[2] = pk2(s[2 * ks + 1][0], s[2 * ks + 1][1]);
                ph[3] = pk2(s[2 * ks + 1][2], s[2 * ks + 1][3]);
                mma16816(o[0], ph, vbh[ks][0], vbh[ks][1]);
                mma16816(o[0], ph, vbl[ks][0], vbl[ks][1]);
                mma16816(o[1], ph, vbh[ks][2], vbh[ks][3]);
                mma16816(o[1], ph, vbl[ks][2], vbl[ks][3]);
            }
            // scale + store O hi/lo to x planes
            int r0 = mt * 16 + g, r1 = r0 + 8;
            u32 sw0 = ((u32)(r0 & 7) << 4), sw1 = ((u32)(r1 & 7) << 4);
#pragma unroll
            for (int nt = 0; nt < 2; nt++) {
                int dc = h * 16 + nt * 8 + t * 2;
                u32 h01, l01, h23, l23;
                split2(o[nt][0] * i0, o[nt][1] * i0, h01, l01);
                split2(o[nt][2] * i1, o[nt][3] * i1, h23, l23);
                u32 o0 = ((u32)(r0 * 128 + dc * 2)) ^ sw0;
                u32 o1 = ((u32)(r1 * 128 + dc * 2)) ^ sw1;
                sts32(sb + AT_XH + o0, h01); sts32(sb + AT_XL + o0, l01);
                sts32(sb + AT_XH + o1, h23); sts32(sb + AT_XL + o1, l23);
            }
        }
    }
    CPASYNC_WAIT0();
    __syncthreads();

    // ---- phase 3: proj GEMM (3-term), warp = (m-tile, n-half) ----
    {
        int mtile = w >> 1, nh = w & 1;
        float c[4][4];
#pragma unroll
        for (int nt = 0; nt < 4; nt++)
#pragma unroll
            for (int e = 0; e < 4; e++) c[nt][e] = 0.0f;
#pragma unroll
        for (int ks = 0; ks < 4; ks++) {
            u32 ah[4], al[4];
            u32 ar = (u32)(mtile * 16 + aRow);
            u32 off = ar * 128 + (u32)(ks * 32) + aKl;
            u32 sw = ((ar & 7) << 4);
            ldsm4(ah, sb + AT_XH + (off ^ sw));
            ldsm4(al, sb + AT_XL + (off ^ sw));
#pragma unroll
            for (int npl = 0; npl < 2; npl++) {
                int np = nh * 2 + npl;
                u32 bh[4], bl[4];
                u32 nr = (u32)(np * 16 + bRow);
                u32 boff = nr * 128 + (u32)(ks * 32) + bKl;
                u32 bsw = ((nr & 7) << 4);
                ldsm4(bh, sb + AT_VTH + (boff ^ bsw));
                ldsm4(bl, sb + AT_VTL + (boff ^ bsw));
                mma16816(c[npl * 2], ah, bh[0], bh[1]);
                mma16816(c[npl * 2], al, bh[0], bh[1]);
                mma16816(c[npl * 2], ah, bl[0], bl[1]);
                mma16816(c[npl * 2 + 1], ah, bh[2], bh[3]);
                mma16816(c[npl * 2 + 1], al, bh[2], bh[3]);
                mma16816(c[npl * 2 + 1], ah, bl[2], bl[3]);
            }
        }
        if (to_h16) {
#pragma unroll
            for (int ntl = 0; ntl < 4; ntl++) {
                int nt = nh * 4 + ntl;
                int cc = nt * 8 + t * 2;
                float b0 = __ldg(projb + cc), b1 = __ldg(projb + cc + 1);
#pragma unroll
                for (int rh = 0; rh < 2; rh++) {
                    int tok = mtile * 16 + g + rh * 8;
                    int ty = tok >> 3, tx = tok & 7;
                    float v0 = c[ntl][rh * 2] + b0, v1 = c[ntl][rh * 2 + 1] + b1;
                    int gy = wy * 8 + ty, gx = wx * 8 + tx;
                    __half* dst = g_h16 +
                        ((size_t)((b * 130 + gy + 1) * 130 + gx + 1)) * 64 + cc;
                    *(__half2*)dst = __floats2half2_rn(v0, v1);
                }
            }
        } else {
            float* s_red = (float*)(smem + AT_RED);    // [4 mtile][2 nh][8 g][2 rh]
            float acc0 = 0.0f, acc1 = 0.0f;
#pragma unroll
            for (int ntl = 0; ntl < 4; ntl++) {
                int cc = (nh * 4 + ntl) * 8 + t * 2;
                float b0 = __ldg(projb + cc), b1 = __ldg(projb + cc + 1);
                float w0 = __ldg(outw + cc), w1 = __ldg(outw + cc + 1);
                acc0 += (c[ntl][0] + b0) * w0 + (c[ntl][1] + b1) * w1;
                acc1 += (c[ntl][2] + b0) * w0 + (c[ntl][3] + b1) * w1;
            }
            acc0 += __shfl_xor_sync(0xffffffff, acc0, 1);
            acc0 += __shfl_xor_sync(0xffffffff, acc0, 2);
            acc1 += __shfl_xor_sync(0xffffffff, acc1, 1);
            acc1 += __shfl_xor_sync(0xffffffff, acc1, 2);
            if (t == 0) {
                s_red[((mtile * 2 + nh) * 8 + g) * 2 + 0] = acc0;
                s_red[((mtile * 2 + nh) * 8 + g) * 2 + 1] = acc1;
            }
            __syncthreads();
            if (tid < 64) {
                int mt2 = tid >> 4, g2 = (tid >> 1) & 7, rh2 = tid & 1;
                float v = s_red[((mt2 * 2 + 0) * 8 + g2) * 2 + rh2] +
                          s_red[((mt2 * 2 + 1) * 8 + g2) * 2 + rh2] + __ldg(outb);
                int tok = mt2 * 16 + g2 + rh2 * 8;
                int ty = tok >> 3, tx = tok & 7;
                int gy = wy * 8 + ty, gx = wx * 8 + tx;
                out[(b * 128 + gy) * 128 + gx] = v;
            }
        }
    }
}

// ---------------------------------------------------------------------------
// Layer 1 conv on mma.sync (round-10 version: full row, 512 thr, 2-stage B)
// ---------------------------------------------------------------------------
#define L1_A_OFF 0
#define L1_A_BYTES (390 * 128)
#define L1_B0 L1_A_BYTES
#define L1_B_BYTES (320 * 128)
#define L1_B1 (L1_B0 + L1_B_BYTES)
#define L1_SMEM_TOTAL (L1_B1 + L1_B_BYTES)   // 131840

__device__ __forceinline__ void l1_load_B(u32 sB, int tap, int tid) {
    if (tid < 320) {
        const __half* src = g_w1h + (size_t)(tap * 320 + tid) * 64;
        u32 row = tid * 128;
        u32 sw = (u32)((tid & 7) << 4);
#pragma unroll
        for (int i = 0; i < 8; i++)
            cp16(sB + ((row + i * 16) ^ sw), (const char*)src + i * 16);
    }
}

__global__ __launch_bounds__(512, 1) void layer1_tc(const float* __restrict__ cb) {
    extern __shared__ char smem[];
    u32 sb = smem_u32(smem);
    int tid = threadIdx.x, lane = tid & 31, warp = tid >> 5;
    int wm = warp & 3, wn = warp >> 2;
    int tile = blockIdx.x;
    int b = tile >> 7, y = tile & 127;

    if (tid < 390) {
        int rowIdx = tid / 130, col = tid % 130;
        const __half* src = g_h16 +
            ((size_t)((b * 130 + y + rowIdx) * 130 + col)) * 64;
        u32 row = (u32)tid * 128;
        u32 sw = (u32)((tid & 7) << 4);
#pragma unroll
        for (int i = 0; i < 8; i++)
            cp16(sb + L1_A_OFF + ((row + i * 16) ^ sw), (const char*)src + i * 16);
    }
    l1_load_B(sb + L1_B0, 0, tid);
    CPASYNC_COMMIT();
    CPASYNC_WAIT0();
    __syncthreads();

    float c[2][5][2][4];
#pragma unroll
    for (int mi = 0; mi < 2; mi++)
#pragma unroll
        for (int g5 = 0; g5 < 5; g5++)
#pragma unroll
            for (int nt = 0; nt < 2; nt++)
#pragma unroll
                for (int e = 0; e < 4; e++) c[mi][g5][nt][e] = 0.0f;

    int arow = wm * 32 + (lane & 7) + 8 * ((lane >> 3) & 1);
    u32 aklane = (u32)(16 * (lane >> 4));
    u32 bkl = (u32)(((lane >> 3) & 1) * 16);
    int bnrow_base = wn * 16 + ((lane >> 4) & 1) * 8 + (lane & 7);
    u32 bswz = (u32)((lane & 7) << 4);

#pragma unroll 1
    for (int tap = 0; tap < 9; tap++) {
        u32 Bb = sb + ((tap & 1) ? L1_B1 : L1_B0);
        if (tap < 8) {
            l1_load_B(sb + ((tap & 1) ? L1_B0 : L1_B1), tap + 1, tid);
            CPASYNC_COMMIT();
        }
        int dy = tap / 3, dx = tap % 3;
        int br0 = dy * 130 + arow + dx;
#pragma unroll
        for (int ks = 0; ks < 4; ks++) {
            u32 a[2][4];
#pragma unroll
            for (int mi = 0; mi < 2; mi++) {
                u32 br = (u32)(br0 + mi * 16);
                u32 off = br * 128 + (u32)(ks * 32) + aklane;
                ldsm4(a[mi], sb + L1_A_OFF + (off ^ ((br & 7) << 4)));
            }
#pragma unroll
            for (int g5 = 0; g5 < 5; g5++) {
                u32 bfr[4];
                u32 nrow = (u32)(g5 * 64 + bnrow_base);
                u32 off = nrow * 128 + (u32)(ks * 32) + bkl;
                ldsm4(bfr, Bb + (off ^ bswz));
#pragma unroll
                for (int mi = 0; mi < 2; mi++) {
                    mma16816(c[mi][g5][0], a[mi], bfr[0], bfr[1]);
                    mma16816(c[mi][g5][1], a[mi], bfr[2], bfr[3]);
                }
            }
        }
        if (tap < 8) { CPASYNC_WAIT0(); }
        __syncthreads();
    }

    int q = lane & 3, gr = lane >> 2;
    int ocB = wn * 16;
#pragma unroll
    for (int mi = 0; mi < 2; mi++) {
#pragma unroll
        for (int rh = 0; rh < 2; rh++) {
            int x = wm * 32 + mi * 16 + gr + rh * 8;
            float* orow = g_buf0 + ((size_t)((b * 128 + y) * 128 + x)) * 64;
#pragma unroll
            for (int nt = 0; nt < 2; nt++) {
#pragma unroll
                for (int e = 0; e < 2; e++) {
                    int oc = ocB + nt * 8 + q * 2 + e;
                    int ai = rh * 2 + e;
                    float ci = c[mi][0][nt][ai];
                    float co = c[mi][1][nt][ai];
                    float cg = c[mi][2][nt][ai];
                    float px = c[mi][3][nt][ai];
                    float py = c[mi][4][nt][ai];
                    float ig = sigm(ci + px + __ldg(cb + oc));
                    float og = sigm(co + py + __ldg(cb + 128 + oc));
                    float gg = ftanh(cg + py + __ldg(cb + 192 + oc));
                    orow[oc] = og * ftanh(ig * gg);
                }
            }
        }
    }
}

// ---------------------------------------------------------------------------
extern "C" void kernel_launch(void* const* d_in, const int* in_sizes, int n_in,
                              void* d_out, int out_size) {
    const float* x      = (const float*)d_in[0];
    const float* cw0    = (const float*)d_in[1];
    const float* cb0    = (const float*)d_in[2];
    const float* pxw0   = (const float*)d_in[3];
    const float* pyw0   = (const float*)d_in[4];
    const float* qkvw0  = (const float*)d_in[5];
    const float* projw0 = (const float*)d_in[6];
    const float* projb0 = (const float*)d_in[7];
    const float* cw1    = (const float*)d_in[8];
    const float* cb1    = (const float*)d_in[9];
    const float* pxw1   = (const float*)d_in[10];
    const float* pyw1   = (const float*)d_in[11];
    const float* qkvw1  = (const float*)d_in[12];
    const float* projw1 = (const float*)d_in[13];
    const float* projb1 = (const float*)d_in[14];
    const float* outw   = (const float*)d_in[15];
    const float* outb   = (const float*)d_in[16];
    float* out = (float*)d_out;

    cudaFuncSetAttribute(win_attn_tc, cudaFuncAttributeMaxDynamicSharedMemorySize,
                         AT_SMEM);
    cudaFuncSetAttribute(layer1_tc, cudaFuncAttributeMaxDynamicSharedMemorySize,
                         L1_SMEM_TOTAL);

    // layer0 (blocks 0..1023) + prep piggyback (blocks 1024..)
    layer0_gates<<<1024 + PREP_BLOCKS, 256>>>(x, cw0, cb0, pxw0, pyw0,
                                              cw1, pxw1, pyw1,
                                              qkvw0, projw0, qkvw1, projw1);
    win_attn_tc<<<4096, 256, AT_SMEM>>>(0, projb0, outw, outb, out, 1); // buf0 -> h16
    layer1_tc<<<2048, 512, L1_SMEM_TOTAL>>>(cb1);                       // h16 -> buf0
    win_attn_tc<<<4096, 256, AT_SMEM>>>(1, projb1, outw, outb, out, 0); // buf0 -> out
}